// round 14
// baseline (speedup 1.0000x reference)
#include <cuda_runtime.h>
#include <cuda_bf16.h>
#include <math.h>

// ---------------------------------------------------------------------------
// STTM: 4-layer transformer, w=192, C=128, NHEAD=4, hd=32
// feat (fp32, d_out): (w, n, C). Self: n in [0,256). fl: n<128, fr: n>=128.
// Activations bf16; LN fused into GEMM A-load; weights pre-converted to bf16;
// pos_enc projections batched (bf16, q-scale folded); attention: no-max
// softmax, interior-fast scatter, swizzled Vt, pair-scoped P and Opart
// barriers; cross epilogue merged with the independent fl-q projection.
// ---------------------------------------------------------------------------

#define W_ 192
#define CC 128

// ------------------------- device scratch ---------------------------------
__device__ __nv_bfloat16 g_qkvh[W_*256*384];
__device__ __nv_bfloat16 g_voh [W_*256*CC];
__device__ __nv_bfloat16 g_proj[8*383*256];
__device__ __nv_bfloat16 g_wbh [4*1024*128];

#define WOFF_SIW 0
#define WOFF_SOW (4*384*128)
#define WOFF_CIW (WOFF_SOW + 4*128*128)
#define WOFF_COW (WOFF_CIW + 4*384*128)

// ------------------------- helpers -----------------------------------------
__device__ __forceinline__ unsigned pack_bf2(float x, float y) {
    __nv_bfloat162 h = __float22bfloat162_rn(make_float2(x, y));
    return *(unsigned*)&h;
}

__device__ __forceinline__ void ldm4(unsigned& r0, unsigned& r1, unsigned& r2, unsigned& r3,
                                     unsigned addr) {
    asm volatile("ldmatrix.sync.aligned.m8n8.x4.shared.b16 {%0,%1,%2,%3},[%4];"
                 : "=r"(r0), "=r"(r1), "=r"(r2), "=r"(r3) : "r"(addr));
}

__device__ __forceinline__ void mma_bf16(float* d, const unsigned* a, unsigned b0, unsigned b1) {
    asm volatile(
        "mma.sync.aligned.m16n8k16.row.col.f32.bf16.bf16.f32 "
        "{%0,%1,%2,%3},{%4,%5,%6,%7},{%8,%9},{%0,%1,%2,%3};"
        : "+f"(d[0]), "+f"(d[1]), "+f"(d[2]), "+f"(d[3])
        : "r"(a[0]), "r"(a[1]), "r"(a[2]), "r"(a[3]), "r"(b0), "r"(b1));
}

// ------------------------- fp32 -> bf16 weight conversion (batched) --------
// blockIdx.y selects segment: 0=s_iw, 1=s_ow, 2=c_iw, 3=c_ow.
__global__ void cvt_bf16_all(const float* __restrict__ s_iw, const float* __restrict__ s_ow,
                             const float* __restrict__ c_iw, const float* __restrict__ c_ow,
                             __nv_bfloat16* __restrict__ wbh)
{
    int seg = blockIdx.y;
    const float* src;
    __nv_bfloat16* dst;
    int n4;
    if (seg == 0)      { src = s_iw; dst = wbh + WOFF_SIW; n4 = 49152; }
    else if (seg == 1) { src = s_ow; dst = wbh + WOFF_SOW; n4 = 16384; }
    else if (seg == 2) { src = c_iw; dst = wbh + WOFF_CIW; n4 = 49152; }
    else               { src = c_ow; dst = wbh + WOFF_COW; n4 = 16384; }
    int i = blockIdx.x * 256 + threadIdx.x;
    if (i >= n4) return;
    float4 v = *(const float4*)(src + i * 4);
    uint2 u; u.x = pack_bf2(v.x, v.y); u.y = pack_bf2(v.z, v.w);
    *(uint2*)(dst + i * 4) = u;
}

// ------------------------- build feat from inputs -------------------------
__global__ void build_feat(const float* __restrict__ L, const float* __restrict__ R,
                           float* __restrict__ feat)
{
    __shared__ float tile[32][33];
    int n = blockIdx.z;
    const float* src = (n < 128) ? L : R;
    int nn = n & 127;
    int h = nn >> 1, b = nn & 1;
    int i = blockIdx.x * 32 + threadIdx.x;
    int c = blockIdx.y * 32 + threadIdx.y;
    tile[threadIdx.y][threadIdx.x] = src[(((size_t)b * 128 + c) * 64 + h) * 192 + i];
    __syncthreads();
    int i2 = blockIdx.x * 32 + threadIdx.y;
    int c2 = blockIdx.y * 32 + threadIdx.x;
    feat[((size_t)i2 * 256 + n) * 128 + c2] = tile[threadIdx.x][threadIdx.y];
}

// ------------------------- batched pos_enc projection ----------------------
__global__ void proj_batch(const float* __restrict__ pos_enc,
                           const float* __restrict__ s_iw, const float* __restrict__ s_ib,
                           const float* __restrict__ c_iw, const float* __restrict__ c_ib,
                           __nv_bfloat16* __restrict__ out)
{
    int z = blockIdx.z, layer = z >> 1;
    const float* B    = ((z & 1) ? c_iw : s_iw) + (size_t)layer * 384 * 128;
    const float* bias = ((z & 1) ? c_ib : s_ib) + layer * 384;
    __nv_bfloat16* C = out + (size_t)z * 383 * 256;
    const int M = 383, N = 256;
    const float qsc = 0.17677669529663687f;

    __shared__ float As[16][68];
    __shared__ float Bs[16][68];
    int tid = threadIdx.x;
    int tx = tid & 15, ty = tid >> 4;
    int rowBase = blockIdx.y * 64;
    int colBase = blockIdx.x * 64;

    float acc[4][4];
    #pragma unroll
    for (int i = 0; i < 4; i++)
        #pragma unroll
        for (int j = 0; j < 4; j++) acc[i][j] = 0.f;

    int lr = tid >> 2;
    int lc = (tid & 3) * 4;
    int ar = rowBase + lr;
    const float* aRowPtr = (ar < M) ? (pos_enc + (size_t)ar * 128) : nullptr;
    int bc = colBase + lr;
    const float* bRowPtr = (bc < N) ? (B + (size_t)bc * 128) : nullptr;

    for (int kt = 0; kt < 8; kt++) {
        int k0 = kt * 16 + lc;
        float4 av = aRowPtr ? *(const float4*)(aRowPtr + k0) : make_float4(0, 0, 0, 0);
        float4 bv = bRowPtr ? *(const float4*)(bRowPtr + k0) : make_float4(0, 0, 0, 0);
        As[lc + 0][lr] = av.x; As[lc + 1][lr] = av.y; As[lc + 2][lr] = av.z; As[lc + 3][lr] = av.w;
        Bs[lc + 0][lr] = bv.x; Bs[lc + 1][lr] = bv.y; Bs[lc + 2][lr] = bv.z; Bs[lc + 3][lr] = bv.w;
        __syncthreads();
        #pragma unroll
        for (int k = 0; k < 16; k++) {
            float a0 = As[k][ty * 4 + 0], a1 = As[k][ty * 4 + 1];
            float a2 = As[k][ty * 4 + 2], a3 = As[k][ty * 4 + 3];
            float b0 = Bs[k][tx * 4 + 0], b1 = Bs[k][tx * 4 + 1];
            float b2 = Bs[k][tx * 4 + 2], b3 = Bs[k][tx * 4 + 3];
            acc[0][0] = fmaf(a0, b0, acc[0][0]); acc[0][1] = fmaf(a0, b1, acc[0][1]);
            acc[0][2] = fmaf(a0, b2, acc[0][2]); acc[0][3] = fmaf(a0, b3, acc[0][3]);
            acc[1][0] = fmaf(a1, b0, acc[1][0]); acc[1][1] = fmaf(a1, b1, acc[1][1]);
            acc[1][2] = fmaf(a1, b2, acc[1][2]); acc[1][3] = fmaf(a1, b3, acc[1][3]);
            acc[2][0] = fmaf(a2, b0, acc[2][0]); acc[2][1] = fmaf(a2, b1, acc[2][1]);
            acc[2][2] = fmaf(a2, b2, acc[2][2]); acc[2][3] = fmaf(a2, b3, acc[2][3]);
            acc[3][0] = fmaf(a3, b0, acc[3][0]); acc[3][1] = fmaf(a3, b1, acc[3][1]);
            acc[3][2] = fmaf(a3, b2, acc[3][2]); acc[3][3] = fmaf(a3, b3, acc[3][3]);
        }
        __syncthreads();
    }

    #pragma unroll
    for (int mi = 0; mi < 4; mi++) {
        int r = rowBase + ty * 4 + mi;
        if (r >= M) continue;
        __nv_bfloat16* cRow = C + (size_t)r * 256;
        #pragma unroll
        for (int ni = 0; ni < 4; ni++) {
            int col = colBase + tx * 4 + ni;
            float v = acc[mi][ni] + bias[col];
            if (col < 128) v *= qsc;
            cRow[col] = __float2bfloat16(v);
        }
    }
}

// ------------------------- bf16 tensor-core GEMM core ----------------------
#define HSMEM (2 * 128 * 128 * 2)

template<int AMODE>
__device__ __forceinline__ void hgemm_body(
    const void* __restrict__ Av, int aN0, int aNW, int aNF,
    const float* __restrict__ lnG, const float* __restrict__ lnB,
    const __nv_bfloat16* __restrict__ B, const float* __restrict__ bias,
    float* __restrict__ C, __nv_bfloat16* __restrict__ Cbf,
    int cN0, int cNW, int cNF, int cPitch,
    int addRes, int scaleLim, int rowBase, int colBase,
    __nv_bfloat16* As, __nv_bfloat16* Bs)
{
    int tid = threadIdx.x;
    int lr = tid >> 1, lkh = tid & 1;
    {
        int ar = rowBase + lr;
        int arow = (ar / aNW) * aNF + aN0 + (ar % aNW);
        const __nv_bfloat16* bp = B + (size_t)(colBase + lr) * 128 + lkh * 64;
        int sw = lr & 7;

        float mean = 0.f, inv = 1.f;
        if (AMODE == 1) {
            const float* ap = (const float*)Av + (size_t)arow * 128 + lkh * 64;
            float s = 0.f, sq = 0.f;
            #pragma unroll
            for (int j = 0; j < 16; j++) {
                float4 v = *(const float4*)(ap + j * 4);
                s += v.x + v.y + v.z + v.w;
                sq += v.x*v.x + v.y*v.y + v.z*v.z + v.w*v.w;
            }
            s  += __shfl_xor_sync(0xffffffffu, s,  1);
            sq += __shfl_xor_sync(0xffffffffu, sq, 1);
            mean = s * (1.f / 128.f);
            float var = sq * (1.f / 128.f) - mean * mean;
            inv = rsqrtf(var + 1e-5f);
        }

        #pragma unroll
        for (int j = 0; j < 8; j++) {
            int c = lkh * 8 + j;
            int cp = c ^ sw;
            uint4 u;
            if (AMODE == 2) {
                const __nv_bfloat16* ap = (const __nv_bfloat16*)Av + (size_t)arow * 128 + lkh * 64;
                u = *(const uint4*)(ap + j * 8);
            } else {
                const float* ap = (const float*)Av + (size_t)arow * 128 + lkh * 64;
                float4 v0 = *(const float4*)(ap + j * 8);
                float4 v1 = *(const float4*)(ap + j * 8 + 4);
                int ch = lkh * 64 + j * 8;
                float4 g0 = *(const float4*)(lnG + ch), g1 = *(const float4*)(lnG + ch + 4);
                float4 b0 = *(const float4*)(lnB + ch), b1 = *(const float4*)(lnB + ch + 4);
                v0.x = (v0.x - mean) * inv * g0.x + b0.x;
                v0.y = (v0.y - mean) * inv * g0.y + b0.y;
                v0.z = (v0.z - mean) * inv * g0.z + b0.z;
                v0.w = (v0.w - mean) * inv * g0.w + b0.w;
                v1.x = (v1.x - mean) * inv * g1.x + b1.x;
                v1.y = (v1.y - mean) * inv * g1.y + b1.y;
                v1.z = (v1.z - mean) * inv * g1.z + b1.z;
                v1.w = (v1.w - mean) * inv * g1.w + b1.w;
                u.x = pack_bf2(v0.x, v0.y); u.y = pack_bf2(v0.z, v0.w);
                u.z = pack_bf2(v1.x, v1.y); u.w = pack_bf2(v1.z, v1.w);
            }
            *(uint4*)&As[lr * 128 + cp * 8] = u;
            *(uint4*)&Bs[lr * 128 + cp * 8] = *(const uint4*)(bp + j * 8);
        }
    }
    __syncthreads();

    int wid = tid >> 5, lane = tid & 31;
    int wm = (wid & 3) * 32;
    int wn = (wid >> 2) * 64;
    int g = lane >> 2, tg = lane & 3;

    float acc[2][8][4];
    #pragma unroll
    for (int mt = 0; mt < 2; mt++)
        #pragma unroll
        for (int nt = 0; nt < 8; nt++)
            #pragma unroll
            for (int q = 0; q < 4; q++) acc[mt][nt][q] = 0.f;

    unsigned asBase = (unsigned)__cvta_generic_to_shared(As);
    unsigned bsBase = (unsigned)__cvta_generic_to_shared(Bs);

    #pragma unroll
    for (int ks = 0; ks < 8; ks++) {
        int c0 = ks * 2;
        unsigned afr[2][4];
        #pragma unroll
        for (int mt = 0; mt < 2; mt++) {
            int row = wm + mt * 16 + (lane & 15);
            int ch = c0 + (lane >> 4);
            unsigned addr = asBase + (unsigned)((row * 128 + ((ch ^ (row & 7)) << 3)) * 2);
            ldm4(afr[mt][0], afr[mt][1], afr[mt][2], afr[mt][3], addr);
        }
        unsigned bfr[8][2];
        #pragma unroll
        for (int p = 0; p < 4; p++) {
            int row = wn + p * 16 + (lane & 7) + ((lane >> 4) << 3);
            int ch = c0 + ((lane >> 3) & 1);
            unsigned addr = bsBase + (unsigned)((row * 128 + ((ch ^ (row & 7)) << 3)) * 2);
            unsigned r0, r1, r2, r3;
            ldm4(r0, r1, r2, r3, addr);
            bfr[p * 2][0] = r0;     bfr[p * 2][1] = r1;
            bfr[p * 2 + 1][0] = r2; bfr[p * 2 + 1][1] = r3;
        }
        #pragma unroll
        for (int mt = 0; mt < 2; mt++)
            #pragma unroll
            for (int nt = 0; nt < 8; nt++)
                mma_bf16(acc[mt][nt], afr[mt], bfr[nt][0], bfr[nt][1]);
    }

    const float qsc = 0.17677669529663687f;
    #pragma unroll
    for (int mt = 0; mt < 2; mt++) {
        int r0g = rowBase + wm + mt * 16 + g;
        #pragma unroll
        for (int half = 0; half < 2; half++) {
            int r = r0g + half * 8;
            int crow = (r / cNW) * cNF + cN0 + (r % cNW);
            #pragma unroll
            for (int nt = 0; nt < 8; nt++) {
                int col = colBase + wn + nt * 8 + 2 * tg;
                float2 b2 = *(const float2*)(bias + col);
                float vx = acc[mt][nt][half * 2 + 0] + b2.x;
                float vy = acc[mt][nt][half * 2 + 1] + b2.y;
                if (Cbf) {
                    if (col < scaleLim) { vx *= qsc; vy *= qsc; }
                    *(unsigned*)(Cbf + (size_t)crow * cPitch + col) = pack_bf2(vx, vy);
                } else {
                    float* cp = C + (size_t)crow * cPitch + col;
                    if (addRes) {
                        float2 old = *(const float2*)cp;
                        vx += old.x; vy += old.y;
                    }
                    float2 o2; o2.x = vx; o2.y = vy;
                    *(float2*)cp = o2;
                }
            }
        }
    }
}

template<int AMODE>
__global__ void __launch_bounds__(256) hgemm(
    const void* __restrict__ Av, int aN0, int aNW, int aNF,
    const float* __restrict__ lnG, const float* __restrict__ lnB,
    const __nv_bfloat16* __restrict__ B, const float* __restrict__ bias,
    float* __restrict__ C, __nv_bfloat16* __restrict__ Cbf,
    int cN0, int cNW, int cNF, int cPitch,
    int addRes, int scaleLim)
{
    extern __shared__ __nv_bfloat16 hsm[];
    hgemm_body<AMODE>(Av, aN0, aNW, aNF, lnG, lnB, B, bias, C, Cbf,
                      cN0, cNW, cNF, cPitch, addRes, scaleLim,
                      blockIdx.y * 128, blockIdx.x * 128, hsm, hsm + 128*128);
}

// Merged cross projections (q from one window, kv from another).
__global__ void __launch_bounds__(256) hgemm_cross(
    const float* __restrict__ feat, int qN0, int kN0,
    const float* __restrict__ lnGq, const float* __restrict__ lnBq,
    const float* __restrict__ lnGk, const float* __restrict__ lnBk,
    const __nv_bfloat16* __restrict__ ciw, const float* __restrict__ cib,
    __nv_bfloat16* __restrict__ outQ, __nv_bfloat16* __restrict__ outKV)
{
    extern __shared__ __nv_bfloat16 hsm[];
    int x = blockIdx.x;
    if (x == 0) {
        hgemm_body<1>(feat, qN0, 128, 256, lnGq, lnBq, ciw, cib,
                      nullptr, outQ, 0, 128, 128, 128, 0, 128,
                      blockIdx.y * 128, 0, hsm, hsm + 128*128);
    } else {
        hgemm_body<1>(feat, kN0, 128, 256, lnGk, lnBk, ciw + 128 * 128, cib + 128,
                      nullptr, outKV, 0, 128, 128, 256, 0, 0,
                      blockIdx.y * 128, (x - 1) * 128, hsm, hsm + 128*128);
    }
}

// Merged post-cross1: x=0 -> out-proj of fr-attention (writes feat rows n>=128),
// x=1 -> fl-q projection (reads feat rows n<128, c_g1) -> qbh. Disjoint feat rows.
__global__ void __launch_bounds__(256) hgemm_post1(
    const __nv_bfloat16* __restrict__ voh,
    const __nv_bfloat16* __restrict__ cow, const float* __restrict__ cob,
    float* __restrict__ feat,
    const float* __restrict__ lnG, const float* __restrict__ lnB,
    const __nv_bfloat16* __restrict__ ciw, const float* __restrict__ cib,
    __nv_bfloat16* __restrict__ outQ)
{
    extern __shared__ __nv_bfloat16 hsm[];
    if (blockIdx.x == 0) {
        // out-proj fr: A = voh bf16 (24576 x 128), residual into feat rows n0=128
        hgemm_body<2>(voh, 0, 128, 128, nullptr, nullptr, cow, cob,
                      feat, nullptr, 128, 128, 256, 128, 1, 0,
                      blockIdx.y * 128, 0, hsm, hsm + 128*128);
    } else {
        // fl q projection: LN(feat rows n0=0; c_g1) @ ciw -> qbh (scaled cols)
        hgemm_body<1>(feat, 0, 128, 256, lnG, lnB, ciw, cib,
                      nullptr, outQ, 0, 128, 128, 128, 0, 128,
                      blockIdx.y * 128, 0, hsm, hsm + 128*128);
    }
}

// ------------------------- bf16 mma attention (48-row blocks) ---------------
#define ATC_SMEM 95616

template<int DSIGN>
__global__ void __launch_bounds__(256, 2) attn_tc(
    const __nv_bfloat16* __restrict__ qPtr, int qPitch, int qOff,
    const __nv_bfloat16* __restrict__ kPtr, int kPitch, int kOff,
    const __nv_bfloat16* __restrict__ vPtr, int vPitch, int vOff,
    const __nv_bfloat16* __restrict__ proj, __nv_bfloat16* __restrict__ vo, int nB)
{
    extern __shared__ char smraw[];
    __nv_bfloat16* Qs  = (__nv_bfloat16*)(smraw);
    __nv_bfloat16* Ks  = (__nv_bfloat16*)(smraw + 3840);
    __nv_bfloat16* PKs = (__nv_bfloat16*)(smraw + 19200);
    __nv_bfloat16* PQs = (__nv_bfloat16*)(smraw + 38400);
    __nv_bfloat16* Vt  = PQs;                       // overlay (after Z2 phase)
    float* Opart = (float*)(smraw + 3840);          // overlay Ks (after QK phase)
    float* Ssm  = (float*)(smraw + 57600);
    float* hsum = (float*)(smraw + 95232);          // [2][48]

    int n = blockIdx.x, e = blockIdx.y;
    int i0 = blockIdx.z * 48;
    int tid = threadIdx.x;
    const int dlo = (DSIGN > 0) ? (144 - i0) : i0;

    // ---- loads: Q, K, PK, PQ — pure bf16 uint4 copies ----
    for (int idx = tid; idx < 48 * 4; idx += 256) {
        int r = idx >> 2, h = (idx & 3) * 8;
        uint4 u = *(const uint4*)(qPtr + (size_t)((i0 + r) * nB + n) * qPitch + qOff + e * 32 + h);
        *(uint4*)&Qs[r * 40 + h] = u;
    }
    for (int idx = tid; idx < 192 * 4; idx += 256) {
        int r = idx >> 2, h = (idx & 3) * 8;
        uint4 u = *(const uint4*)(kPtr + (size_t)(r * nB + n) * kPitch + kOff + e * 32 + h);
        *(uint4*)&Ks[r * 40 + h] = u;
    }
    for (int idx = tid; idx < 240 * 4; idx += 256) {
        int t = idx >> 2, h = (idx & 3) * 8;
        int d = dlo + t;
        uint4 zk = make_uint4(0, 0, 0, 0), zq = make_uint4(0, 0, 0, 0);
        if (d < 383) {
            zk = *(const uint4*)(proj + (size_t)d * 256 + 128 + e * 32 + h);
            zq = *(const uint4*)(proj + (size_t)d * 256 + e * 32 + h);
        }
        *(uint4*)&PKs[t * 40 + h] = zk;
        *(uint4*)&PQs[t * 40 + h] = zq;
    }
    __syncthreads();

    int wid = tid >> 5, lane = tid & 31;
    int g = lane >> 2, tg = lane & 3;
    unsigned qBase  = (unsigned)__cvta_generic_to_shared(Qs);
    unsigned kBase  = (unsigned)__cvta_generic_to_shared(Ks);
    unsigned pkBase = (unsigned)__cvta_generic_to_shared(PKs);
    unsigned pqBase = (unsigned)__cvta_generic_to_shared(PQs);
    unsigned vtBase = (unsigned)__cvta_generic_to_shared(Vt);
    unsigned pBase  = (unsigned)__cvta_generic_to_shared(Ssm);

    // ---- Z1 = Q @ PK^T, skew-scattered (init): 3 m-tiles x 13 n16-tiles ----
    #pragma unroll 2
    for (int u = wid; u < 39; u += 8) {
        int mt = u / 13, nt = u % 13;
        int t0m = (DSIGN > 0) ? (32 - 16 * mt) : (16 * mt);
        int tb = t0m + nt * 16;
        unsigned a[2][4], b[2][4];
        #pragma unroll
        for (int ks = 0; ks < 2; ks++) {
            unsigned addrA = qBase + (unsigned)((mt * 16 + (lane & 15)) * 80 + (ks * 2 + (lane >> 4)) * 16);
            ldm4(a[ks][0], a[ks][1], a[ks][2], a[ks][3], addrA);
            int row = tb + (lane & 7) + ((lane >> 4) << 3);
            unsigned addrB = pkBase + (unsigned)(row * 80 + (ks * 2 + ((lane >> 3) & 1)) * 16);
            ldm4(b[ks][0], b[ks][1], b[ks][2], b[ks][3], addrB);
        }
        float acc[2][4];
        #pragma unroll
        for (int h = 0; h < 2; h++) { acc[h][0] = acc[h][1] = acc[h][2] = acc[h][3] = 0.f; }
        mma_bf16(acc[0], a[0], b[0][0], b[0][1]); mma_bf16(acc[0], a[1], b[1][0], b[1][1]);
        mma_bf16(acc[1], a[0], b[0][2], b[0][3]); mma_bf16(acc[1], a[1], b[1][2], b[1][3]);

        if (nt >= 1 && nt <= 11) {
            #pragma unroll
            for (int h = 0; h < 2; h++) {
                int t = tb + h * 8 + 2 * tg;
                #pragma unroll
                for (int rr = 0; rr < 2; rr++) {
                    int il = mt * 16 + g + 8 * rr;
                    float* row = &Ssm[il * 196];
                    if (DSIGN > 0) {
                        int j0 = t + il - 47;
                        row[j0]     = acc[h][rr * 2 + 0];
                        row[j0 + 1] = acc[h][rr * 2 + 1];
                    } else {
                        int j0 = 191 + il - t;
                        row[j0]     = acc[h][rr * 2 + 0];
                        row[j0 - 1] = acc[h][rr * 2 + 1];
                    }
                }
            }
        } else {
            #pragma unroll
            for (int h = 0; h < 2; h++) {
                int t = tb + h * 8 + 2 * tg;
                #pragma unroll
                for (int rr = 0; rr < 2; rr++) {
                    int il = mt * 16 + g + 8 * rr;
                    int j0 = (DSIGN > 0) ? (t + il - 47) : (191 + il - t);
                    int j1 = (DSIGN > 0) ? (j0 + 1) : (j0 - 1);
                    if ((unsigned)j0 < 192u) Ssm[il * 196 + j0] = acc[h][rr * 2 + 0];
                    if ((unsigned)j1 < 192u) Ssm[il * 196 + j1] = acc[h][rr * 2 + 1];
                }
            }
        }
    }
    __syncthreads();

    // ---- Z2 = K @ PQ^T, skew scatter-ADD: 12 j-tiles x 4 n16-tiles ----
    #pragma unroll 2
    for (int u = wid; u < 48; u += 8) {
        int jt = u >> 2, nt = u & 3;
        int t0m = (DSIGN > 0) ? (16 * jt) : (176 - 16 * jt);
        int tb = t0m + nt * 16;
        unsigned a[2][4], b[2][4];
        #pragma unroll
        for (int ks = 0; ks < 2; ks++) {
            unsigned addrA = kBase + (unsigned)((jt * 16 + (lane & 15)) * 80 + (ks * 2 + (lane >> 4)) * 16);
            ldm4(a[ks][0], a[ks][1], a[ks][2], a[ks][3], addrA);
            int row = tb + (lane & 7) + ((lane >> 4) << 3);
            unsigned addrB = pqBase + (unsigned)(row * 80 + (ks * 2 + ((lane >> 3) & 1)) * 16);
            ldm4(b[ks][0], b[ks][1], b[ks][2], b[ks][3], addrB);
        }
        float acc[2][4];
        #pragma unroll
        for (int h = 0; h < 2; h++) { acc[h][0] = acc[h][1] = acc[h][2] = acc[h][3] = 0.f; }
        mma_bf16(acc[0], a[0], b[0][0], b[0][1]); mma_bf16(acc[0], a[1], b[1][0], b[1][1]);
        mma_bf16(acc[1], a[0], b[0][2], b[0][3]); mma_bf16(acc[1], a[1], b[1][2], b[1][3]);

        if (nt == 1 || nt == 2) {
            #pragma unroll
            for (int h = 0; h < 2; h++) {
                int t = tb + h * 8 + 2 * tg;
                #pragma unroll
                for (int rr = 0; rr < 2; rr++) {
                    int j = jt * 16 + g + 8 * rr;
                    int il0 = (DSIGN > 0) ? (47 + j - t) : (t + j - 191);
                    int il1 = (DSIGN > 0) ? (il0 - 1) : (il0 + 1);
                    Ssm[il0 * 196 + j] += acc[h][rr * 2 + 0];
                    Ssm[il1 * 196 + j] += acc[h][rr * 2 + 1];
                }
            }
        } else {
            #pragma unroll
            for (int h = 0; h < 2; h++) {
                int t = tb + h * 8 + 2 * tg;
                #pragma unroll
                for (int rr = 0; rr < 2; rr++) {
                    int j = jt * 16 + g + 8 * rr;
                    int il0 = (DSIGN > 0) ? (47 + j - t) : (t + j - 191);
                    int il1 = (DSIGN > 0) ? (il0 - 1) : (il0 + 1);
                    if ((unsigned)il0 < 48u) Ssm[il0 * 196 + j] += acc[h][rr * 2 + 0];
                    if ((unsigned)il1 < 48u) Ssm[il1 * 196 + j] += acc[h][rr * 2 + 1];
                }
            }
        }
    }
    __syncthreads();

    // ---- warps 0-5: QK^T + gather + exp + partial sums. warps 6-7: Vt ----
    float acc[12][4];
    int mt = wid >> 1, chalf = wid & 1;
    int ilA = mt * 16 + g, ilB = ilA + 8;
    if (wid < 6) {
        #pragma unroll
        for (int nt = 0; nt < 12; nt++)
            #pragma unroll
            for (int q = 0; q < 4; q++) acc[nt][q] = 0.f;

        unsigned a[2][4];
        #pragma unroll
        for (int ks = 0; ks < 2; ks++) {
            unsigned addrA = qBase + (unsigned)((mt * 16 + (lane & 15)) * 80 + (ks * 2 + (lane >> 4)) * 16);
            ldm4(a[ks][0], a[ks][1], a[ks][2], a[ks][3], addrA);
        }
        #pragma unroll
        for (int nt16 = 0; nt16 < 6; nt16++) {
            unsigned b[2][4];
            #pragma unroll
            for (int ks = 0; ks < 2; ks++) {
                int row = chalf * 96 + nt16 * 16 + (lane & 7) + ((lane >> 4) << 3);
                unsigned addrB = kBase + (unsigned)(row * 80 + (ks * 2 + ((lane >> 3) & 1)) * 16);
                ldm4(b[ks][0], b[ks][1], b[ks][2], b[ks][3], addrB);
            }
            mma_bf16(acc[nt16 * 2],     a[0], b[0][0], b[0][1]);
            mma_bf16(acc[nt16 * 2],     a[1], b[1][0], b[1][1]);
            mma_bf16(acc[nt16 * 2 + 1], a[0], b[0][2], b[0][3]);
            mma_bf16(acc[nt16 * 2 + 1], a[1], b[1][2], b[1][3]);
        }

        float sA = 0.f, sB = 0.f;
        #pragma unroll
        for (int nt = 0; nt < 12; nt++) {
            int j = chalf * 96 + nt * 8 + 2 * tg;
            float2 zA = *(const float2*)&Ssm[ilA * 196 + j];
            float2 zB = *(const float2*)&Ssm[ilB * 196 + j];
            acc[nt][0] = __expf(fminf(acc[nt][0] + zA.x, 70.f)); sA += acc[nt][0];
            acc[nt][1] = __expf(fminf(acc[nt][1] + zA.y, 70.f)); sA += acc[nt][1];
            acc[nt][2] = __expf(fminf(acc[nt][2] + zB.x, 70.f)); sB += acc[nt][2];
            acc[nt][3] = __expf(fminf(acc[nt][3] + zB.y, 70.f)); sB += acc[nt][3];
        }
        sA += __shfl_xor_sync(0xffffffffu, sA, 1);
        sA += __shfl_xor_sync(0xffffffffu, sA, 2);
        sB += __shfl_xor_sync(0xffffffffu, sB, 1);
        sB += __shfl_xor_sync(0xffffffffu, sB, 2);
        if (tg == 0) {
            hsum[chalf * 48 + ilA] = sA;
            hsum[chalf * 48 + ilB] = sB;
        }
    } else {
        // transpose-load V into dead PQs region; XOR-swizzled j-chunks
        for (int idx = tid - 192; idx < 192 * 4; idx += 64) {
            int j = idx >> 2, c8 = (idx & 3) * 8;
            uint4 u = *(const uint4*)(vPtr + (size_t)(j * nB + n) * vPitch + vOff + e * 32 + c8);
            __nv_bfloat16 tmp[8];
            *(uint4*)tmp = u;
            int chunk = j >> 3, jo = j & 7;
            #pragma unroll
            for (int k = 0; k < 8; k++) {
                int row = c8 + k;
                int cs = chunk ^ ((row >> 3) & 3);
                Vt[row * 200 + cs * 8 + jo] = tmp[k];
            }
        }
    }
    // full barrier: hsum exchange + Vt visibility for PV (warps 6-7's last barrier)
    __syncthreads();

    // ---- normalize, write P (packed bf16 over Ssm); pair-scoped barrier ----
    if (wid < 6) {
        float invA = 1.f / (hsum[ilA] + hsum[48 + ilA]);
        float invB = 1.f / (hsum[ilB] + hsum[48 + ilB]);
        unsigned* Pw = (unsigned*)Ssm;
        #pragma unroll
        for (int nt = 0; nt < 12; nt++) {
            int cw = chalf * 48 + nt * 4 + tg;
            Pw[ilA * 196 + cw] = pack_bf2(acc[nt][0] * invA, acc[nt][1] * invA);
            Pw[ilB * 196 + cw] = pack_bf2(acc[nt][2] * invB, acc[nt][3] * invB);
        }
        // sync only the pair (2mt, 2mt+1) that produced/consume P tile mt
        asm volatile("bar.sync %0, 64;" :: "r"(mt + 1) : "memory");

        // ---- O = P @ V : 6 warps (3 m-tiles x 2 k-halves) ----
        float oacc[4][4];
        #pragma unroll
        for (int t = 0; t < 4; t++)
            #pragma unroll
            for (int q = 0; q < 4; q++) oacc[t][q] = 0.f;

        #pragma unroll 2
        for (int s = 0; s < 6; s++) {
            int ks = chalf * 6 + s;
            unsigned a[4];
            unsigned addrA = pBase + (unsigned)((mt * 16 + (lane & 15)) * 784 + (ks * 2 + (lane >> 4)) * 16);
            ldm4(a[0], a[1], a[2], a[3], addrA);
            #pragma unroll
            for (int nb = 0; nb < 2; nb++) {
                int row = nb * 16 + (lane & 7) + ((lane >> 4) << 3);
                int chunk = ks * 2 + ((lane >> 3) & 1);
                int cs = chunk ^ ((row >> 3) & 3);
                unsigned addrB = vtBase + (unsigned)(row * 400 + cs * 16);
                unsigned b0, b1, b2, b3;
                ldm4(b0, b1, b2, b3, addrB);
                mma_bf16(oacc[nb * 2],     a, b0, b1);
                mma_bf16(oacc[nb * 2 + 1], a, b2, b3);
            }
        }
        if (chalf == 1) {
            #pragma unroll
            for (int t = 0; t < 4; t++) {
                int c = t * 8 + 2 * tg;
                Opart[ilA * 32 + c]     = oacc[t][0];
                Opart[ilA * 32 + c + 1] = oacc[t][1];
                Opart[ilB * 32 + c]     = oacc[t][2];
                Opart[ilB * 32 + c + 1] = oacc[t][3];
            }
        }
        // pair-scoped: Opart tile mt written by warp 2mt+1, read by warp 2mt
        asm volatile("bar.sync %0, 64;" :: "r"(mt + 1) : "memory");

        if (chalf == 0) {
            int iA = i0 + ilA, iB = i0 + ilB;
            size_t oA = (size_t)(iA * nB + n) * 128 + e * 32;
            size_t oB = (size_t)(iB * nB + n) * 128 + e * 32;
            #pragma unroll
            for (int t = 0; t < 4; t++) {
                int c = t * 8 + 2 * tg;
                *(unsigned*)(vo + oA + c) = pack_bf2(oacc[t][0] + Opart[ilA * 32 + c],
                                                     oacc[t][1] + Opart[ilA * 32 + c + 1]);
                *(unsigned*)(vo + oB + c) = pack_bf2(oacc[t][2] + Opart[ilB * 32 + c],
                                                     oacc[t][3] + Opart[ilB * 32 + c + 1]);
            }
        }
    }
}

// ---------------------------------------------------------------------------
extern "C" void kernel_launch(void* const* d_in, const int* in_sizes, int n_in,
                              void* d_out, int out_size)
{
    (void)in_sizes; (void)n_in; (void)out_size;
    const float* feat_left  = (const float*)d_in[0];
    const float* feat_right = (const float*)d_in[1];
    const float* pos_enc    = (const float*)d_in[2];
    const float* s_iw = (const float*)d_in[3];
    const float* s_ib = (const float*)d_in[4];
    const float* s_ow = (const float*)d_in[5];
    const float* s_ob = (const float*)d_in[6];
    const float* s_g  = (const float*)d_in[7];
    const float* s_b  = (const float*)d_in[8];
    const float* c_iw = (const float*)d_in[9];
    const float* c_ib = (const float*)d_in[10];
    const float* c_ow = (const float*)d_in[11];
    const float* c_ob = (const float*)d_in[12];
    const float* c_g1 = (const float*)d_in[13];
    const float* c_b1 = (const float*)d_in[14];
    const float* c_g2 = (const float*)d_in[15];
    const float* c_b2 = (const float*)d_in[16];

    float* feat = (float*)d_out;

    __nv_bfloat16 *qkvh, *voh, *projb, *wbh;
    cudaGetSymbolAddress((void**)&qkvh, g_qkvh);
    cudaGetSymbolAddress((void**)&voh, g_voh);
    cudaGetSymbolAddress((void**)&projb, g_proj);
    cudaGetSymbolAddress((void**)&wbh, g_wbh);
    __nv_bfloat16* qbh  = qkvh;
    __nv_bfloat16* kvbh = qkvh + 192 * 128 * 128;

    cudaFuncSetAttribute(attn_tc<1>,  cudaFuncAttributeMaxDynamicSharedMemorySize, ATC_SMEM);
    cudaFuncSetAttribute(attn_tc<-1>, cudaFuncAttributeMaxDynamicSharedMemorySize, ATC_SMEM);
    cudaFuncSetAttribute(hgemm<1>, cudaFuncAttributeMaxDynamicSharedMemorySize, HSMEM);
    cudaFuncSetAttribute(hgemm<2>, cudaFuncAttributeMaxDynamicSharedMemorySize, HSMEM);
    cudaFuncSetAttribute(hgemm_cross, cudaFuncAttributeMaxDynamicSharedMemorySize, HSMEM);
    cudaFuncSetAttribute(hgemm_post1, cudaFuncAttributeMaxDynamicSharedMemorySize, HSMEM);

    build_feat<<<dim3(6, 4, 256), dim3(32, 32)>>>(feat_left, feat_right, feat);
    proj_batch<<<dim3(4, 6, 8), 256>>>(pos_enc, s_iw, s_ib, c_iw, c_ib, projb);
    cvt_bf16_all<<<dim3(192, 4), 256>>>(s_iw, s_ow, c_iw, c_ow, wbh);

    for (int L = 0; L < 4; L++) {
        const __nv_bfloat16* siwH = wbh + WOFF_SIW + (size_t)L * 384 * 128;
        const __nv_bfloat16* sowH = wbh + WOFF_SOW + (size_t)L * 128 * 128;
        const __nv_bfloat16* ciwH = wbh + WOFF_CIW + (size_t)L * 384 * 128;
        const __nv_bfloat16* cowH = wbh + WOFF_COW + (size_t)L * 128 * 128;
        const float* sib = s_ib + (size_t)L * 384;
        const float* sob = s_ob + (size_t)L * 128;
        const float* cib = c_ib + (size_t)L * 384;
        const float* cob = c_ob + (size_t)L * 128;
        const __nv_bfloat16* projS = projb + (size_t)(L * 2) * 383 * 256;
        const __nv_bfloat16* projC = projb + (size_t)(L * 2 + 1) * 383 * 256;

        // ---------------- self-attention ----------------
        hgemm<1><<<dim3(3, 384), 256, HSMEM>>>(feat, 0, 256, 256,
                                               s_g + L * 128, s_b + L * 128,
                                               siwH, sib, nullptr, qkvh,
                                               0, 256, 256, 384, 0, 128);
        attn_tc<1><<<dim3(256, 4, 4), 256, ATC_SMEM>>>(qkvh, 384, 0, qkvh, 384, 128,
                                                       qkvh, 384, 256, projS, voh, 256);
        hgemm<2><<<dim3(1, 384), 256, HSMEM>>>(voh, 0, 256, 256, nullptr, nullptr,
                                               sowH, sob, feat, nullptr,
                                               0, 256, 256, 128, 1, 0);

        // ---------------- cross-attention ----------------
        // fr update: q = LN(fr; c_g1), kv = LN(fl; c_g1), flipped table
        hgemm_cross<<<dim3(3, 192), 256, HSMEM>>>(feat, 128, 0,
                                                  c_g1 + L * 128, c_b1 + L * 128,
                                                  c_g1 + L * 128, c_b1 + L * 128,
                                                  ciwH, cib, qbh, kvbh);
        attn_tc<-1><<<dim3(128, 4, 4), 256, ATC_SMEM>>>(qbh, 128, 0, kvbh, 256, 0,
                                                        kvbh, 256, 128, projC, voh, 128);
        // merged: out-proj fr (rows n>=128) || fl q projection (rows n<128)
        hgemm_post1<<<dim3(2, 192), 256, HSMEM>>>(voh, cowH, cob, feat,
                                                  c_g1 + L * 128, c_b1 + L * 128,
                                                  ciwH, cib, qbh);
        // kv = LN(updated fr; c_g2)
        hgemm<1><<<dim3(2, 192), 256, HSMEM>>>(feat, 128, 128, 256,
                                               c_g2 + L * 128, c_b2 + L * 128,
                                               ciwH + 128 * 128, cib + 128, nullptr, kvbh,
                                               0, 128, 128, 256, 0, 0);
        attn_tc<1><<<dim3(128, 4, 4), 256, ATC_SMEM>>>(qbh, 128, 0, kvbh, 256, 0,
                                                       kvbh, 256, 128, projC, voh, 128);
        hgemm<2><<<dim3(1, 192), 256, HSMEM>>>(voh, 0, 128, 128, nullptr, nullptr,
                                               cowH, cob, feat, nullptr,
                                               0, 128, 256, 128, 1, 0);
    }
}

// round 15
// speedup vs baseline: 1.1295x; 1.1295x over previous
#include <cuda_runtime.h>
#include <cuda_bf16.h>
#include <math.h>

// ---------------------------------------------------------------------------
// STTM: 4-layer transformer, w=192, C=128, NHEAD=4, hd=32
// feat (fp32, d_out): (w, n, C). Self: n in [0,256). fl: n<128, fr: n>=128.
// Activations bf16; LN fused into GEMM A-load (B via cp.async overlap);
// weights pre-converted to bf16; pos_enc projections batched (bf16, q-scale
// folded); attention: shared PK/PQ buffer -> 74.6KB smem -> 3 blocks/SM,
// no-max softmax, interior-fast scatter, swizzled Vt, pair-scoped barriers.
// ---------------------------------------------------------------------------

#define W_ 192
#define CC 128

// ------------------------- device scratch ---------------------------------
__device__ __nv_bfloat16 g_qkvh[W_*256*384];
__device__ __nv_bfloat16 g_voh [W_*256*CC];
__device__ __nv_bfloat16 g_proj[8*383*256];
__device__ __nv_bfloat16 g_wbh [4*1024*128];

#define WOFF_SIW 0
#define WOFF_SOW (4*384*128)
#define WOFF_CIW (WOFF_SOW + 4*128*128)
#define WOFF_COW (WOFF_CIW + 4*384*128)

// ------------------------- helpers -----------------------------------------
__device__ __forceinline__ unsigned pack_bf2(float x, float y) {
    __nv_bfloat162 h = __float22bfloat162_rn(make_float2(x, y));
    return *(unsigned*)&h;
}

__device__ __forceinline__ void ldm4(unsigned& r0, unsigned& r1, unsigned& r2, unsigned& r3,
                                     unsigned addr) {
    asm volatile("ldmatrix.sync.aligned.m8n8.x4.shared.b16 {%0,%1,%2,%3},[%4];"
                 : "=r"(r0), "=r"(r1), "=r"(r2), "=r"(r3) : "r"(addr));
}

__device__ __forceinline__ void mma_bf16(float* d, const unsigned* a, unsigned b0, unsigned b1) {
    asm volatile(
        "mma.sync.aligned.m16n8k16.row.col.f32.bf16.bf16.f32 "
        "{%0,%1,%2,%3},{%4,%5,%6,%7},{%8,%9},{%0,%1,%2,%3};"
        : "+f"(d[0]), "+f"(d[1]), "+f"(d[2]), "+f"(d[3])
        : "r"(a[0]), "r"(a[1]), "r"(a[2]), "r"(a[3]), "r"(b0), "r"(b1));
}

__device__ __forceinline__ void cpasync16(unsigned dst, const void* src) {
    asm volatile("cp.async.cg.shared.global [%0], [%1], 16;" :: "r"(dst), "l"(src));
}

// ------------------------- fp32 -> bf16 weight conversion (batched) --------
__global__ void cvt_bf16_all(const float* __restrict__ s_iw, const float* __restrict__ s_ow,
                             const float* __restrict__ c_iw, const float* __restrict__ c_ow,
                             __nv_bfloat16* __restrict__ wbh)
{
    int seg = blockIdx.y;
    const float* src;
    __nv_bfloat16* dst;
    int n4;
    if (seg == 0)      { src = s_iw; dst = wbh + WOFF_SIW; n4 = 49152; }
    else if (seg == 1) { src = s_ow; dst = wbh + WOFF_SOW; n4 = 16384; }
    else if (seg == 2) { src = c_iw; dst = wbh + WOFF_CIW; n4 = 49152; }
    else               { src = c_ow; dst = wbh + WOFF_COW; n4 = 16384; }
    int i = blockIdx.x * 256 + threadIdx.x;
    if (i >= n4) return;
    float4 v = *(const float4*)(src + i * 4);
    uint2 u; u.x = pack_bf2(v.x, v.y); u.y = pack_bf2(v.z, v.w);
    *(uint2*)(dst + i * 4) = u;
}

// ------------------------- build feat from inputs -------------------------
__global__ void build_feat(const float* __restrict__ L, const float* __restrict__ R,
                           float* __restrict__ feat)
{
    __shared__ float tile[32][33];
    int n = blockIdx.z;
    const float* src = (n < 128) ? L : R;
    int nn = n & 127;
    int h = nn >> 1, b = nn & 1;
    int i = blockIdx.x * 32 + threadIdx.x;
    int c = blockIdx.y * 32 + threadIdx.y;
    tile[threadIdx.y][threadIdx.x] = src[(((size_t)b * 128 + c) * 64 + h) * 192 + i];
    __syncthreads();
    int i2 = blockIdx.x * 32 + threadIdx.y;
    int c2 = blockIdx.y * 32 + threadIdx.x;
    feat[((size_t)i2 * 256 + n) * 128 + c2] = tile[threadIdx.x][threadIdx.y];
}

// ------------------------- batched pos_enc projection ----------------------
__global__ void proj_batch(const float* __restrict__ pos_enc,
                           const float* __restrict__ s_iw, const float* __restrict__ s_ib,
                           const float* __restrict__ c_iw, const float* __restrict__ c_ib,
                           __nv_bfloat16* __restrict__ out)
{
    int z = blockIdx.z, layer = z >> 1;
    const float* B    = ((z & 1) ? c_iw : s_iw) + (size_t)layer * 384 * 128;
    const float* bias = ((z & 1) ? c_ib : s_ib) + layer * 384;
    __nv_bfloat16* C = out + (size_t)z * 383 * 256;
    const int M = 383, N = 256;
    const float qsc = 0.17677669529663687f;

    __shared__ float As[16][68];
    __shared__ float Bs[16][68];
    int tid = threadIdx.x;
    int tx = tid & 15, ty = tid >> 4;
    int rowBase = blockIdx.y * 64;
    int colBase = blockIdx.x * 64;

    float acc[4][4];
    #pragma unroll
    for (int i = 0; i < 4; i++)
        #pragma unroll
        for (int j = 0; j < 4; j++) acc[i][j] = 0.f;

    int lr = tid >> 2;
    int lc = (tid & 3) * 4;
    int ar = rowBase + lr;
    const float* aRowPtr = (ar < M) ? (pos_enc + (size_t)ar * 128) : nullptr;
    int bc = colBase + lr;
    const float* bRowPtr = (bc < N) ? (B + (size_t)bc * 128) : nullptr;

    for (int kt = 0; kt < 8; kt++) {
        int k0 = kt * 16 + lc;
        float4 av = aRowPtr ? *(const float4*)(aRowPtr + k0) : make_float4(0, 0, 0, 0);
        float4 bv = bRowPtr ? *(const float4*)(bRowPtr + k0) : make_float4(0, 0, 0, 0);
        As[lc + 0][lr] = av.x; As[lc + 1][lr] = av.y; As[lc + 2][lr] = av.z; As[lc + 3][lr] = av.w;
        Bs[lc + 0][lr] = bv.x; Bs[lc + 1][lr] = bv.y; Bs[lc + 2][lr] = bv.z; Bs[lc + 3][lr] = bv.w;
        __syncthreads();
        #pragma unroll
        for (int k = 0; k < 16; k++) {
            float a0 = As[k][ty * 4 + 0], a1 = As[k][ty * 4 + 1];
            float a2 = As[k][ty * 4 + 2], a3 = As[k][ty * 4 + 3];
            float b0 = Bs[k][tx * 4 + 0], b1 = Bs[k][tx * 4 + 1];
            float b2 = Bs[k][tx * 4 + 2], b3 = Bs[k][tx * 4 + 3];
            acc[0][0] = fmaf(a0, b0, acc[0][0]); acc[0][1] = fmaf(a0, b1, acc[0][1]);
            acc[0][2] = fmaf(a0, b2, acc[0][2]); acc[0][3] = fmaf(a0, b3, acc[0][3]);
            acc[1][0] = fmaf(a1, b0, acc[1][0]); acc[1][1] = fmaf(a1, b1, acc[1][1]);
            acc[1][2] = fmaf(a1, b2, acc[1][2]); acc[1][3] = fmaf(a1, b3, acc[1][3]);
            acc[2][0] = fmaf(a2, b0, acc[2][0]); acc[2][1] = fmaf(a2, b1, acc[2][1]);
            acc[2][2] = fmaf(a2, b2, acc[2][2]); acc[2][3] = fmaf(a2, b3, acc[2][3]);
            acc[3][0] = fmaf(a3, b0, acc[3][0]); acc[3][1] = fmaf(a3, b1, acc[3][1]);
            acc[3][2] = fmaf(a3, b2, acc[3][2]); acc[3][3] = fmaf(a3, b3, acc[3][3]);
        }
        __syncthreads();
    }

    #pragma unroll
    for (int mi = 0; mi < 4; mi++) {
        int r = rowBase + ty * 4 + mi;
        if (r >= M) continue;
        __nv_bfloat16* cRow = C + (size_t)r * 256;
        #pragma unroll
        for (int ni = 0; ni < 4; ni++) {
            int col = colBase + tx * 4 + ni;
            float v = acc[mi][ni] + bias[col];
            if (col < 128) v *= qsc;
            cRow[col] = __float2bfloat16(v);
        }
    }
}

// ------------------------- bf16 tensor-core GEMM core ----------------------
#define HSMEM (2 * 128 * 128 * 2)

template<int AMODE>
__device__ __forceinline__ void hgemm_body(
    const void* __restrict__ Av, int aN0, int aNW, int aNF,
    const float* __restrict__ lnG, const float* __restrict__ lnB,
    const __nv_bfloat16* __restrict__ B, const float* __restrict__ bias,
    float* __restrict__ C, __nv_bfloat16* __restrict__ Cbf,
    int cN0, int cNW, int cNF, int cPitch,
    int addRes, int scaleLim, int rowBase, int colBase,
    __nv_bfloat16* As, __nv_bfloat16* Bs)
{
    int tid = threadIdx.x;
    unsigned asBase = (unsigned)__cvta_generic_to_shared(As);
    unsigned bsBase = (unsigned)__cvta_generic_to_shared(Bs);
    int lr = tid >> 1, lkh = tid & 1;
    {
        int ar = rowBase + lr;
        int arow = (ar / aNW) * aNF + aN0 + (ar % aNW);
        const __nv_bfloat16* bp = B + (size_t)(colBase + lr) * 128 + lkh * 64;
        int sw = lr & 7;

        // ---- B via cp.async (overlaps with A processing below) ----
        #pragma unroll
        for (int j = 0; j < 8; j++) {
            int cp = (lkh * 8 + j) ^ sw;
            cpasync16(bsBase + (unsigned)((lr * 128 + cp * 8) * 2), bp + j * 8);
        }
        asm volatile("cp.async.commit_group;");

        float mean = 0.f, inv = 1.f;
        if (AMODE == 1) {
            const float* ap = (const float*)Av + (size_t)arow * 128 + lkh * 64;
            float s = 0.f, sq = 0.f;
            #pragma unroll
            for (int j = 0; j < 16; j++) {
                float4 v = *(const float4*)(ap + j * 4);
                s += v.x + v.y + v.z + v.w;
                sq += v.x*v.x + v.y*v.y + v.z*v.z + v.w*v.w;
            }
            s  += __shfl_xor_sync(0xffffffffu, s,  1);
            sq += __shfl_xor_sync(0xffffffffu, sq, 1);
            mean = s * (1.f / 128.f);
            float var = sq * (1.f / 128.f) - mean * mean;
            inv = rsqrtf(var + 1e-5f);
        }

        #pragma unroll
        for (int j = 0; j < 8; j++) {
            int c = lkh * 8 + j;
            int cp = c ^ sw;
            if (AMODE == 2) {
                const __nv_bfloat16* ap = (const __nv_bfloat16*)Av + (size_t)arow * 128 + lkh * 64;
                cpasync16(asBase + (unsigned)((lr * 128 + cp * 8) * 2), ap + j * 8);
            } else {
                const float* ap = (const float*)Av + (size_t)arow * 128 + lkh * 64;
                float4 v0 = *(const float4*)(ap + j * 8);
                float4 v1 = *(const float4*)(ap + j * 8 + 4);
                int ch = lkh * 64 + j * 8;
                float4 g0 = *(const float4*)(lnG + ch), g1 = *(const float4*)(lnG + ch + 4);
                float4 b0 = *(const float4*)(lnB + ch), b1 = *(const float4*)(lnB + ch + 4);
                v0.x = (v0.x - mean) * inv * g0.x + b0.x;
                v0.y = (v0.y - mean) * inv * g0.y + b0.y;
                v0.z = (v0.z - mean) * inv * g0.z + b0.z;
                v0.w = (v0.w - mean) * inv * g0.w + b0.w;
                v1.x = (v1.x - mean) * inv * g1.x + b1.x;
                v1.y = (v1.y - mean) * inv * g1.y + b1.y;
                v1.z = (v1.z - mean) * inv * g1.z + b1.z;
                v1.w = (v1.w - mean) * inv * g1.w + b1.w;
                uint4 u;
                u.x = pack_bf2(v0.x, v0.y); u.y = pack_bf2(v0.z, v0.w);
                u.z = pack_bf2(v1.x, v1.y); u.w = pack_bf2(v1.z, v1.w);
                *(uint4*)&As[lr * 128 + cp * 8] = u;
            }
        }
        if (AMODE == 2) asm volatile("cp.async.commit_group;");
        asm volatile("cp.async.wait_group 0;");
    }
    __syncthreads();

    int wid = tid >> 5, lane = tid & 31;
    int wm = (wid & 3) * 32;
    int wn = (wid >> 2) * 64;
    int g = lane >> 2, tg = lane & 3;

    float acc[2][8][4];
    #pragma unroll
    for (int mt = 0; mt < 2; mt++)
        #pragma unroll
        for (int nt = 0; nt < 8; nt++)
            #pragma unroll
            for (int q = 0; q < 4; q++) acc[mt][nt][q] = 0.f;

    #pragma unroll
    for (int ks = 0; ks < 8; ks++) {
        int c0 = ks * 2;
        unsigned afr[2][4];
        #pragma unroll
        for (int mt = 0; mt < 2; mt++) {
            int row = wm + mt * 16 + (lane & 15);
            int ch = c0 + (lane >> 4);
            unsigned addr = asBase + (unsigned)((row * 128 + ((ch ^ (row & 7)) << 3)) * 2);
            ldm4(afr[mt][0], afr[mt][1], afr[mt][2], afr[mt][3], addr);
        }
        unsigned bfr[8][2];
        #pragma unroll
        for (int p = 0; p < 4; p++) {
            int row = wn + p * 16 + (lane & 7) + ((lane >> 4) << 3);
            int ch = c0 + ((lane >> 3) & 1);
            unsigned addr = bsBase + (unsigned)((row * 128 + ((ch ^ (row & 7)) << 3)) * 2);
            unsigned r0, r1, r2, r3;
            ldm4(r0, r1, r2, r3, addr);
            bfr[p * 2][0] = r0;     bfr[p * 2][1] = r1;
            bfr[p * 2 + 1][0] = r2; bfr[p * 2 + 1][1] = r3;
        }
        #pragma unroll
        for (int mt = 0; mt < 2; mt++)
            #pragma unroll
            for (int nt = 0; nt < 8; nt++)
                mma_bf16(acc[mt][nt], afr[mt], bfr[nt][0], bfr[nt][1]);
    }

    const float qsc = 0.17677669529663687f;
    #pragma unroll
    for (int mt = 0; mt < 2; mt++) {
        int r0g = rowBase + wm + mt * 16 + g;
        #pragma unroll
        for (int half = 0; half < 2; half++) {
            int r = r0g + half * 8;
            int crow = (r / cNW) * cNF + cN0 + (r % cNW);
            #pragma unroll
            for (int nt = 0; nt < 8; nt++) {
                int col = colBase + wn + nt * 8 + 2 * tg;
                float2 b2 = *(const float2*)(bias + col);
                float vx = acc[mt][nt][half * 2 + 0] + b2.x;
                float vy = acc[mt][nt][half * 2 + 1] + b2.y;
                if (Cbf) {
                    if (col < scaleLim) { vx *= qsc; vy *= qsc; }
                    *(unsigned*)(Cbf + (size_t)crow * cPitch + col) = pack_bf2(vx, vy);
                } else {
                    float* cp = C + (size_t)crow * cPitch + col;
                    if (addRes) {
                        float2 old = *(const float2*)cp;
                        vx += old.x; vy += old.y;
                    }
                    float2 o2; o2.x = vx; o2.y = vy;
                    *(float2*)cp = o2;
                }
            }
        }
    }
}

template<int AMODE>
__global__ void __launch_bounds__(256) hgemm(
    const void* __restrict__ Av, int aN0, int aNW, int aNF,
    const float* __restrict__ lnG, const float* __restrict__ lnB,
    const __nv_bfloat16* __restrict__ B, const float* __restrict__ bias,
    float* __restrict__ C, __nv_bfloat16* __restrict__ Cbf,
    int cN0, int cNW, int cNF, int cPitch,
    int addRes, int scaleLim)
{
    extern __shared__ __nv_bfloat16 hsm[];
    hgemm_body<AMODE>(Av, aN0, aNW, aNF, lnG, lnB, B, bias, C, Cbf,
                      cN0, cNW, cNF, cPitch, addRes, scaleLim,
                      blockIdx.y * 128, blockIdx.x * 128, hsm, hsm + 128*128);
}

__global__ void __launch_bounds__(256) hgemm_cross(
    const float* __restrict__ feat, int qN0, int kN0,
    const float* __restrict__ lnGq, const float* __restrict__ lnBq,
    const float* __restrict__ lnGk, const float* __restrict__ lnBk,
    const __nv_bfloat16* __restrict__ ciw, const float* __restrict__ cib,
    __nv_bfloat16* __restrict__ outQ, __nv_bfloat16* __restrict__ outKV)
{
    extern __shared__ __nv_bfloat16 hsm[];
    int x = blockIdx.x;
    if (x == 0) {
        hgemm_body<1>(feat, qN0, 128, 256, lnGq, lnBq, ciw, cib,
                      nullptr, outQ, 0, 128, 128, 128, 0, 128,
                      blockIdx.y * 128, 0, hsm, hsm + 128*128);
    } else {
        hgemm_body<1>(feat, kN0, 128, 256, lnGk, lnBk, ciw + 128 * 128, cib + 128,
                      nullptr, outKV, 0, 128, 128, 256, 0, 0,
                      blockIdx.y * 128, (x - 1) * 128, hsm, hsm + 128*128);
    }
}

// Merged post-cross1: x=0 -> out-proj of fr-attention (rows n>=128),
// x=1 -> fl-q projection (rows n<128). Disjoint feat rows.
__global__ void __launch_bounds__(256) hgemm_post1(
    const __nv_bfloat16* __restrict__ voh,
    const __nv_bfloat16* __restrict__ cow, const float* __restrict__ cob,
    float* __restrict__ feat,
    const float* __restrict__ lnG, const float* __restrict__ lnB,
    const __nv_bfloat16* __restrict__ ciw, const float* __restrict__ cib,
    __nv_bfloat16* __restrict__ outQ)
{
    extern __shared__ __nv_bfloat16 hsm[];
    if (blockIdx.x == 0) {
        hgemm_body<2>(voh, 0, 128, 128, nullptr, nullptr, cow, cob,
                      feat, nullptr, 128, 128, 256, 128, 1, 0,
                      blockIdx.y * 128, 0, hsm, hsm + 128*128);
    } else {
        hgemm_body<1>(feat, 0, 128, 256, lnG, lnB, ciw, cib,
                      nullptr, outQ, 0, 128, 128, 128, 0, 128,
                      blockIdx.y * 128, 0, hsm, hsm + 128*128);
    }
}

// ------------------------- bf16 mma attention (48-row blocks) ---------------
// smem: Qs@0 (3840), Ks@3840 (15360; Opart overlays), PBs@19200 (19200:
//   PK for Z1, then PQ for Z2, then Vt), Ssm@38400 (37632 -> packed P),
//   hsum@76032 (384). Total 76416 -> 3 blocks/SM.
#define ATC_SMEM 76416

template<int DSIGN>
__global__ void __launch_bounds__(256, 3) attn_tc(
    const __nv_bfloat16* __restrict__ qPtr, int qPitch, int qOff,
    const __nv_bfloat16* __restrict__ kPtr, int kPitch, int kOff,
    const __nv_bfloat16* __restrict__ vPtr, int vPitch, int vOff,
    const __nv_bfloat16* __restrict__ proj, __nv_bfloat16* __restrict__ vo, int nB)
{
    extern __shared__ char smraw[];
    __nv_bfloat16* Qs  = (__nv_bfloat16*)(smraw);
    __nv_bfloat16* Ks  = (__nv_bfloat16*)(smraw + 3840);
    __nv_bfloat16* PBs = (__nv_bfloat16*)(smraw + 19200);  // PK -> PQ -> Vt
    __nv_bfloat16* Vt  = PBs;
    float* Opart = (float*)(smraw + 3840);                 // overlay Ks
    float* Ssm  = (float*)(smraw + 38400);
    float* hsum = (float*)(smraw + 76032);                 // [2][48]

    int n = blockIdx.x, e = blockIdx.y;
    int i0 = blockIdx.z * 48;
    int tid = threadIdx.x;
    const int dlo = (DSIGN > 0) ? (144 - i0) : i0;

    // ---- loads: Q, K, PK — pure bf16 uint4 copies ----
    for (int idx = tid; idx < 48 * 4; idx += 256) {
        int r = idx >> 2, h = (idx & 3) * 8;
        uint4 u = *(const uint4*)(qPtr + (size_t)((i0 + r) * nB + n) * qPitch + qOff + e * 32 + h);
        *(uint4*)&Qs[r * 40 + h] = u;
    }
    for (int idx = tid; idx < 192 * 4; idx += 256) {
        int r = idx >> 2, h = (idx & 3) * 8;
        uint4 u = *(const uint4*)(kPtr + (size_t)(r * nB + n) * kPitch + kOff + e * 32 + h);
        *(uint4*)&Ks[r * 40 + h] = u;
    }
    for (int idx = tid; idx < 240 * 4; idx += 256) {
        int t = idx >> 2, h = (idx & 3) * 8;
        int d = dlo + t;
        uint4 zk = make_uint4(0, 0, 0, 0);
        if (d < 383) zk = *(const uint4*)(proj + (size_t)d * 256 + 128 + e * 32 + h);
        *(uint4*)&PBs[t * 40 + h] = zk;
    }
    __syncthreads();

    int wid = tid >> 5, lane = tid & 31;
    int g = lane >> 2, tg = lane & 3;
    unsigned qBase  = (unsigned)__cvta_generic_to_shared(Qs);
    unsigned kBase  = (unsigned)__cvta_generic_to_shared(Ks);
    unsigned pbBase = (unsigned)__cvta_generic_to_shared(PBs);
    unsigned vtBase = pbBase;
    unsigned pBase  = (unsigned)__cvta_generic_to_shared(Ssm);

    // ---- Z1 = Q @ PK^T, skew-scattered (init): 3 m-tiles x 13 n16-tiles ----
    #pragma unroll 2
    for (int u = wid; u < 39; u += 8) {
        int mt = u / 13, nt = u % 13;
        int t0m = (DSIGN > 0) ? (32 - 16 * mt) : (16 * mt);
        int tb = t0m + nt * 16;
        unsigned a[2][4], b[2][4];
        #pragma unroll
        for (int ks = 0; ks < 2; ks++) {
            unsigned addrA = qBase + (unsigned)((mt * 16 + (lane & 15)) * 80 + (ks * 2 + (lane >> 4)) * 16);
            ldm4(a[ks][0], a[ks][1], a[ks][2], a[ks][3], addrA);
            int row = tb + (lane & 7) + ((lane >> 4) << 3);
            unsigned addrB = pbBase + (unsigned)(row * 80 + (ks * 2 + ((lane >> 3) & 1)) * 16);
            ldm4(b[ks][0], b[ks][1], b[ks][2], b[ks][3], addrB);
        }
        float acc[2][4];
        #pragma unroll
        for (int h = 0; h < 2; h++) { acc[h][0] = acc[h][1] = acc[h][2] = acc[h][3] = 0.f; }
        mma_bf16(acc[0], a[0], b[0][0], b[0][1]); mma_bf16(acc[0], a[1], b[1][0], b[1][1]);
        mma_bf16(acc[1], a[0], b[0][2], b[0][3]); mma_bf16(acc[1], a[1], b[1][2], b[1][3]);

        if (nt >= 1 && nt <= 11) {
            #pragma unroll
            for (int h = 0; h < 2; h++) {
                int t = tb + h * 8 + 2 * tg;
                #pragma unroll
                for (int rr = 0; rr < 2; rr++) {
                    int il = mt * 16 + g + 8 * rr;
                    float* row = &Ssm[il * 196];
                    if (DSIGN > 0) {
                        int j0 = t + il - 47;
                        row[j0]     = acc[h][rr * 2 + 0];
                        row[j0 + 1] = acc[h][rr * 2 + 1];
                    } else {
                        int j0 = 191 + il - t;
                        row[j0]     = acc[h][rr * 2 + 0];
                        row[j0 - 1] = acc[h][rr * 2 + 1];
                    }
                }
            }
        } else {
            #pragma unroll
            for (int h = 0; h < 2; h++) {
                int t = tb + h * 8 + 2 * tg;
                #pragma unroll
                for (int rr = 0; rr < 2; rr++) {
                    int il = mt * 16 + g + 8 * rr;
                    int j0 = (DSIGN > 0) ? (t + il - 47) : (191 + il - t);
                    int j1 = (DSIGN > 0) ? (j0 + 1) : (j0 - 1);
                    if ((unsigned)j0 < 192u) Ssm[il * 196 + j0] = acc[h][rr * 2 + 0];
                    if ((unsigned)j1 < 192u) Ssm[il * 196 + j1] = acc[h][rr * 2 + 1];
                }
            }
        }
    }
    __syncthreads();

    // ---- reload shared buffer with PQ ----
    for (int idx = tid; idx < 240 * 4; idx += 256) {
        int t = idx >> 2, h = (idx & 3) * 8;
        int d = dlo + t;
        uint4 zq = make_uint4(0, 0, 0, 0);
        if (d < 383) zq = *(const uint4*)(proj + (size_t)d * 256 + e * 32 + h);
        *(uint4*)&PBs[t * 40 + h] = zq;
    }
    __syncthreads();

    // ---- Z2 = K @ PQ^T, skew scatter-ADD: 12 j-tiles x 4 n16-tiles ----
    #pragma unroll 2
    for (int u = wid; u < 48; u += 8) {
        int jt = u >> 2, nt = u & 3;
        int t0m = (DSIGN > 0) ? (16 * jt) : (176 - 16 * jt);
        int tb = t0m + nt * 16;
        unsigned a[2][4], b[2][4];
        #pragma unroll
        for (int ks = 0; ks < 2; ks++) {
            unsigned addrA = kBase + (unsigned)((jt * 16 + (lane & 15)) * 80 + (ks * 2 + (lane >> 4)) * 16);
            ldm4(a[ks][0], a[ks][1], a[ks][2], a[ks][3], addrA);
            int row = tb + (lane & 7) + ((lane >> 4) << 3);
            unsigned addrB = pbBase + (unsigned)(row * 80 + (ks * 2 + ((lane >> 3) & 1)) * 16);
            ldm4(b[ks][0], b[ks][1], b[ks][2], b[ks][3], addrB);
        }
        float acc[2][4];
        #pragma unroll
        for (int h = 0; h < 2; h++) { acc[h][0] = acc[h][1] = acc[h][2] = acc[h][3] = 0.f; }
        mma_bf16(acc[0], a[0], b[0][0], b[0][1]); mma_bf16(acc[0], a[1], b[1][0], b[1][1]);
        mma_bf16(acc[1], a[0], b[0][2], b[0][3]); mma_bf16(acc[1], a[1], b[1][2], b[1][3]);

        if (nt == 1 || nt == 2) {
            #pragma unroll
            for (int h = 0; h < 2; h++) {
                int t = tb + h * 8 + 2 * tg;
                #pragma unroll
                for (int rr = 0; rr < 2; rr++) {
                    int j = jt * 16 + g + 8 * rr;
                    int il0 = (DSIGN > 0) ? (47 + j - t) : (t + j - 191);
                    int il1 = (DSIGN > 0) ? (il0 - 1) : (il0 + 1);
                    Ssm[il0 * 196 + j] += acc[h][rr * 2 + 0];
                    Ssm[il1 * 196 + j] += acc[h][rr * 2 + 1];
                }
            }
        } else {
            #pragma unroll
            for (int h = 0; h < 2; h++) {
                int t = tb + h * 8 + 2 * tg;
                #pragma unroll
                for (int rr = 0; rr < 2; rr++) {
                    int j = jt * 16 + g + 8 * rr;
                    int il0 = (DSIGN > 0) ? (47 + j - t) : (t + j - 191);
                    int il1 = (DSIGN > 0) ? (il0 - 1) : (il0 + 1);
                    if ((unsigned)il0 < 48u) Ssm[il0 * 196 + j] += acc[h][rr * 2 + 0];
                    if ((unsigned)il1 < 48u) Ssm[il1 * 196 + j] += acc[h][rr * 2 + 1];
                }
            }
        }
    }
    __syncthreads();

    // ---- warps 0-5: QK^T + gather + exp + partial sums. warps 6-7: Vt ----
    float acc[12][4];
    int mt = wid >> 1, chalf = wid & 1;
    int ilA = mt * 16 + g, ilB = ilA + 8;
    if (wid < 6) {
        #pragma unroll
        for (int nt = 0; nt < 12; nt++)
            #pragma unroll
            for (int q = 0; q < 4; q++) acc[nt][q] = 0.f;

        unsigned a[2][4];
        #pragma unroll
        for (int ks = 0; ks < 2; ks++) {
            unsigned addrA = qBase + (unsigned)((mt * 16 + (lane & 15)) * 80 + (ks * 2 + (lane >> 4)) * 16);
            ldm4(a[ks][0], a[ks][1], a[ks][2], a[ks][3], addrA);
        }
        #pragma unroll
        for (int nt16 = 0; nt16 < 6; nt16++) {
            unsigned b[2][4];
            #pragma unroll
            for (int ks = 0; ks < 2; ks++) {
                int row = chalf * 96 + nt16 * 16 + (lane & 7) + ((lane >> 4) << 3);
                unsigned addrB = kBase + (unsigned)(row * 80 + (ks * 2 + ((lane >> 3) & 1)) * 16);
                ldm4(b[ks][0], b[ks][1], b[ks][2], b[ks][3], addrB);
            }
            mma_bf16(acc[nt16 * 2],     a[0], b[0][0], b[0][1]);
            mma_bf16(acc[nt16 * 2],     a[1], b[1][0], b[1][1]);
            mma_bf16(acc[nt16 * 2 + 1], a[0], b[0][2], b[0][3]);
            mma_bf16(acc[nt16 * 2 + 1], a[1], b[1][2], b[1][3]);
        }

        float sA = 0.f, sB = 0.f;
        #pragma unroll
        for (int nt = 0; nt < 12; nt++) {
            int j = chalf * 96 + nt * 8 + 2 * tg;
            float2 zA = *(const float2*)&Ssm[ilA * 196 + j];
            float2 zB = *(const float2*)&Ssm[ilB * 196 + j];
            acc[nt][0] = __expf(fminf(acc[nt][0] + zA.x, 70.f)); sA += acc[nt][0];
            acc[nt][1] = __expf(fminf(acc[nt][1] + zA.y, 70.f)); sA += acc[nt][1];
            acc[nt][2] = __expf(fminf(acc[nt][2] + zB.x, 70.f)); sB += acc[nt][2];
            acc[nt][3] = __expf(fminf(acc[nt][3] + zB.y, 70.f)); sB += acc[nt][3];
        }
        sA += __shfl_xor_sync(0xffffffffu, sA, 1);
        sA += __shfl_xor_sync(0xffffffffu, sA, 2);
        sB += __shfl_xor_sync(0xffffffffu, sB, 1);
        sB += __shfl_xor_sync(0xffffffffu, sB, 2);
        if (tg == 0) {
            hsum[chalf * 48 + ilA] = sA;
            hsum[chalf * 48 + ilB] = sB;
        }
    } else {
        // transpose-load V into the dead PBs region; XOR-swizzled j-chunks
        for (int idx = tid - 192; idx < 192 * 4; idx += 64) {
            int j = idx >> 2, c8 = (idx & 3) * 8;
            uint4 u = *(const uint4*)(vPtr + (size_t)(j * nB + n) * vPitch + vOff + e * 32 + c8);
            __nv_bfloat16 tmp[8];
            *(uint4*)tmp = u;
            int chunk = j >> 3, jo = j & 7;
            #pragma unroll
            for (int k = 0; k < 8; k++) {
                int row = c8 + k;
                int cs = chunk ^ ((row >> 3) & 3);
                Vt[row * 200 + cs * 8 + jo] = tmp[k];
            }
        }
    }
    __syncthreads();

    // ---- normalize, write P (packed bf16 over Ssm); pair-scoped barriers ----
    if (wid < 6) {
        float invA = 1.f / (hsum[ilA] + hsum[48 + ilA]);
        float invB = 1.f / (hsum[ilB] + hsum[48 + ilB]);
        unsigned* Pw = (unsigned*)Ssm;
        #pragma unroll
        for (int nt = 0; nt < 12; nt++) {
            int cw = chalf * 48 + nt * 4 + tg;
            Pw[ilA * 196 + cw] = pack_bf2(acc[nt][0] * invA, acc[nt][1] * invA);
            Pw[ilB * 196 + cw] = pack_bf2(acc[nt][2] * invB, acc[nt][3] * invB);
        }
        asm volatile("bar.sync %0, 64;" :: "r"(mt + 1) : "memory");

        // ---- O = P @ V : 6 warps (3 m-tiles x 2 k-halves) ----
        float oacc[4][4];
        #pragma unroll
        for (int t = 0; t < 4; t++)
            #pragma unroll
            for (int q = 0; q < 4; q++) oacc[t][q] = 0.f;

        #pragma unroll 2
        for (int s = 0; s < 6; s++) {
            int ks = chalf * 6 + s;
            unsigned a[4];
            unsigned addrA = pBase + (unsigned)((mt * 16 + (lane & 15)) * 784 + (ks * 2 + (lane >> 4)) * 16);
            ldm4(a[0], a[1], a[2], a[3], addrA);
            #pragma unroll
            for (int nb = 0; nb < 2; nb++) {
                int row = nb * 16 + (lane & 7) + ((lane >> 4) << 3);
                int chunk = ks * 2 + ((lane >> 3) & 1);
                int cs = chunk ^ ((row >> 3) & 3);
                unsigned addrB = vtBase + (unsigned)(row * 400 + cs * 16);
                unsigned b0, b1, b2, b3;
                ldm4(b0, b1, b2, b3, addrB);
                mma_bf16(oacc[nb * 2],     a, b0, b1);
                mma_bf16(oacc[nb * 2 + 1], a, b2, b3);
            }
        }
        if (chalf == 1) {
            #pragma unroll
            for (int t = 0; t < 4; t++) {
                int c = t * 8 + 2 * tg;
                Opart[ilA * 32 + c]     = oacc[t][0];
                Opart[ilA * 32 + c + 1] = oacc[t][1];
                Opart[ilB * 32 + c]     = oacc[t][2];
                Opart[ilB * 32 + c + 1] = oacc[t][3];
            }
        }
        asm volatile("bar.sync %0, 64;" :: "r"(mt + 1) : "memory");

        if (chalf == 0) {
            int iA = i0 + ilA, iB = i0 + ilB;
            size_t oA = (size_t)(iA * nB + n) * 128 + e * 32;
            size_t oB = (size_t)(iB * nB + n) * 128 + e * 32;
            #pragma unroll
            for (int t = 0; t < 4; t++) {
                int c = t * 8 + 2 * tg;
                *(unsigned*)(vo + oA + c) = pack_bf2(oacc[t][0] + Opart[ilA * 32 + c],
                                                     oacc[t][1] + Opart[ilA * 32 + c + 1]);
                *(unsigned*)(vo + oB + c) = pack_bf2(oacc[t][2] + Opart[ilB * 32 + c],
                                                     oacc[t][3] + Opart[ilB * 32 + c + 1]);
            }
        }
    }
}

// ---------------------------------------------------------------------------
extern "C" void kernel_launch(void* const* d_in, const int* in_sizes, int n_in,
                              void* d_out, int out_size)
{
    (void)in_sizes; (void)n_in; (void)out_size;
    const float* feat_left  = (const float*)d_in[0];
    const float* feat_right = (const float*)d_in[1];
    const float* pos_enc    = (const float*)d_in[2];
    const float* s_iw = (const float*)d_in[3];
    const float* s_ib = (const float*)d_in[4];
    const float* s_ow = (const float*)d_in[5];
    const float* s_ob = (const float*)d_in[6];
    const float* s_g  = (const float*)d_in[7];
    const float* s_b  = (const float*)d_in[8];
    const float* c_iw = (const float*)d_in[9];
    const float* c_ib = (const float*)d_in[10];
    const float* c_ow = (const float*)d_in[11];
    const float* c_ob = (const float*)d_in[12];
    const float* c_g1 = (const float*)d_in[13];
    const float* c_b1 = (const float*)d_in[14];
    const float* c_g2 = (const float*)d_in[15];
    const float* c_b2 = (const float*)d_in[16];

    float* feat = (float*)d_out;

    __nv_bfloat16 *qkvh, *voh, *projb, *wbh;
    cudaGetSymbolAddress((void**)&qkvh, g_qkvh);
    cudaGetSymbolAddress((void**)&voh, g_voh);
    cudaGetSymbolAddress((void**)&projb, g_proj);
    cudaGetSymbolAddress((void**)&wbh, g_wbh);
    __nv_bfloat16* qbh  = qkvh;
    __nv_bfloat16* kvbh = qkvh + 192 * 128 * 128;

    cudaFuncSetAttribute(attn_tc<1>,  cudaFuncAttributeMaxDynamicSharedMemorySize, ATC_SMEM);
    cudaFuncSetAttribute(attn_tc<-1>, cudaFuncAttributeMaxDynamicSharedMemorySize, ATC_SMEM);
    cudaFuncSetAttribute(hgemm<1>, cudaFuncAttributeMaxDynamicSharedMemorySize, HSMEM);
    cudaFuncSetAttribute(hgemm<2>, cudaFuncAttributeMaxDynamicSharedMemorySize, HSMEM);
    cudaFuncSetAttribute(hgemm_cross, cudaFuncAttributeMaxDynamicSharedMemorySize, HSMEM);
    cudaFuncSetAttribute(hgemm_post1, cudaFuncAttributeMaxDynamicSharedMemorySize, HSMEM);

    build_feat<<<dim3(6, 4, 256), dim3(32, 32)>>>(feat_left, feat_right, feat);
    proj_batch<<<dim3(4, 6, 8), 256>>>(pos_enc, s_iw, s_ib, c_iw, c_ib, projb);
    cvt_bf16_all<<<dim3(192, 4), 256>>>(s_iw, s_ow, c_iw, c_ow, wbh);

    for (int L = 0; L < 4; L++) {
        const __nv_bfloat16* siwH = wbh + WOFF_SIW + (size_t)L * 384 * 128;
        const __nv_bfloat16* sowH = wbh + WOFF_SOW + (size_t)L * 128 * 128;
        const __nv_bfloat16* ciwH = wbh + WOFF_CIW + (size_t)L * 384 * 128;
        const __nv_bfloat16* cowH = wbh + WOFF_COW + (size_t)L * 128 * 128;
        const float* sib = s_ib + (size_t)L * 384;
        const float* sob = s_ob + (size_t)L * 128;
        const float* cib = c_ib + (size_t)L * 384;
        const float* cob = c_ob + (size_t)L * 128;
        const __nv_bfloat16* projS = projb + (size_t)(L * 2) * 383 * 256;
        const __nv_bfloat16* projC = projb + (size_t)(L * 2 + 1) * 383 * 256;

        // ---------------- self-attention ----------------
        hgemm<1><<<dim3(3, 384), 256, HSMEM>>>(feat, 0, 256, 256,
                                               s_g + L * 128, s_b + L * 128,
                                               siwH, sib, nullptr, qkvh,
                                               0, 256, 256, 384, 0, 128);
        attn_tc<1><<<dim3(256, 4, 4), 256, ATC_SMEM>>>(qkvh, 384, 0, qkvh, 384, 128,
                                                       qkvh, 384, 256, projS, voh, 256);
        hgemm<2><<<dim3(1, 384), 256, HSMEM>>>(voh, 0, 256, 256, nullptr, nullptr,
                                               sowH, sob, feat, nullptr,
                                               0, 256, 256, 128, 1, 0);

        // ---------------- cross-attention ----------------
        hgemm_cross<<<dim3(3, 192), 256, HSMEM>>>(feat, 128, 0,
                                                  c_g1 + L * 128, c_b1 + L * 128,
                                                  c_g1 + L * 128, c_b1 + L * 128,
                                                  ciwH, cib, qbh, kvbh);
        attn_tc<-1><<<dim3(128, 4, 4), 256, ATC_SMEM>>>(qbh, 128, 0, kvbh, 256, 0,
                                                        kvbh, 256, 128, projC, voh, 128);
        hgemm_post1<<<dim3(2, 192), 256, HSMEM>>>(voh, cowH, cob, feat,
                                                  c_g1 + L * 128, c_b1 + L * 128,
                                                  ciwH, cib, qbh);
        hgemm<1><<<dim3(2, 192), 256, HSMEM>>>(feat, 128, 128, 256,
                                               c_g2 + L * 128, c_b2 + L * 128,
                                               ciwH + 128 * 128, cib + 128, nullptr, kvbh,
                                               0, 128, 128, 256, 0, 0);
        attn_tc<1><<<dim3(128, 4, 4), 256, ATC_SMEM>>>(qbh, 128, 0, kvbh, 256, 0,
                                                       kvbh, 256, 128, projC, voh, 128);
        hgemm<2><<<dim3(1, 192), 256, HSMEM>>>(voh, 0, 128, 128, nullptr, nullptr,
                                               cowH, cob, feat, nullptr,
                                               0, 128, 256, 128, 1, 0);
    }
}

// round 16
// speedup vs baseline: 1.2450x; 1.1023x over previous
#include <cuda_runtime.h>
#include <cuda_bf16.h>
#include <math.h>

// ---------------------------------------------------------------------------
// STTM: 4-layer transformer, w=192, C=128, NHEAD=4, hd=32
// feat (fp32, d_out): (w, n, C). Self: n in [0,256). fl: n<128, fr: n>=128.
// Activations bf16; LN fused into GEMM A-load (B via cp.async overlap);
// weights pre-converted to bf16; pos_enc projections batched (bf16, q-scale
// folded); attention: shared PK/PQ buffer (3 blocks/SM), cp.async copy
// phases, no-max softmax, interior-fast scatter, swizzled Vt, pair barriers.
// ---------------------------------------------------------------------------

#define W_ 192
#define CC 128

// ------------------------- device scratch ---------------------------------
__device__ __nv_bfloat16 g_qkvh[W_*256*384];
__device__ __nv_bfloat16 g_voh [W_*256*CC];
__device__ __nv_bfloat16 g_proj[8*383*256];
__device__ __nv_bfloat16 g_wbh [4*1024*128];

#define WOFF_SIW 0
#define WOFF_SOW (4*384*128)
#define WOFF_CIW (WOFF_SOW + 4*128*128)
#define WOFF_COW (WOFF_CIW + 4*384*128)

// ------------------------- helpers -----------------------------------------
__device__ __forceinline__ unsigned pack_bf2(float x, float y) {
    __nv_bfloat162 h = __float22bfloat162_rn(make_float2(x, y));
    return *(unsigned*)&h;
}

__device__ __forceinline__ void ldm4(unsigned& r0, unsigned& r1, unsigned& r2, unsigned& r3,
                                     unsigned addr) {
    asm volatile("ldmatrix.sync.aligned.m8n8.x4.shared.b16 {%0,%1,%2,%3},[%4];"
                 : "=r"(r0), "=r"(r1), "=r"(r2), "=r"(r3) : "r"(addr));
}

__device__ __forceinline__ void mma_bf16(float* d, const unsigned* a, unsigned b0, unsigned b1) {
    asm volatile(
        "mma.sync.aligned.m16n8k16.row.col.f32.bf16.bf16.f32 "
        "{%0,%1,%2,%3},{%4,%5,%6,%7},{%8,%9},{%0,%1,%2,%3};"
        : "+f"(d[0]), "+f"(d[1]), "+f"(d[2]), "+f"(d[3])
        : "r"(a[0]), "r"(a[1]), "r"(a[2]), "r"(a[3]), "r"(b0), "r"(b1));
}

__device__ __forceinline__ void cpasync16(unsigned dst, const void* src) {
    asm volatile("cp.async.cg.shared.global [%0], [%1], 16;" :: "r"(dst), "l"(src));
}
// zfill variant: copies n bytes (n in {0,16}), zero-fills the rest of 16.
__device__ __forceinline__ void cpasync16z(unsigned dst, const void* src, int n) {
    asm volatile("cp.async.cg.shared.global [%0], [%1], 16, %2;"
                 :: "r"(dst), "l"(src), "r"(n));
}

// ------------------------- fp32 -> bf16 weight conversion (batched) --------
__global__ void cvt_bf16_all(const float* __restrict__ s_iw, const float* __restrict__ s_ow,
                             const float* __restrict__ c_iw, const float* __restrict__ c_ow,
                             __nv_bfloat16* __restrict__ wbh)
{
    int seg = blockIdx.y;
    const float* src;
    __nv_bfloat16* dst;
    int n4;
    if (seg == 0)      { src = s_iw; dst = wbh + WOFF_SIW; n4 = 49152; }
    else if (seg == 1) { src = s_ow; dst = wbh + WOFF_SOW; n4 = 16384; }
    else if (seg == 2) { src = c_iw; dst = wbh + WOFF_CIW; n4 = 49152; }
    else               { src = c_ow; dst = wbh + WOFF_COW; n4 = 16384; }
    int i = blockIdx.x * 256 + threadIdx.x;
    if (i >= n4) return;
    float4 v = *(const float4*)(src + i * 4);
    uint2 u; u.x = pack_bf2(v.x, v.y); u.y = pack_bf2(v.z, v.w);
    *(uint2*)(dst + i * 4) = u;
}

// ------------------------- build feat from inputs -------------------------
__global__ void build_feat(const float* __restrict__ L, const float* __restrict__ R,
                           float* __restrict__ feat)
{
    __shared__ float tile[32][33];
    int n = blockIdx.z;
    const float* src = (n < 128) ? L : R;
    int nn = n & 127;
    int h = nn >> 1, b = nn & 1;
    int i = blockIdx.x * 32 + threadIdx.x;
    int c = blockIdx.y * 32 + threadIdx.y;
    tile[threadIdx.y][threadIdx.x] = src[(((size_t)b * 128 + c) * 64 + h) * 192 + i];
    __syncthreads();
    int i2 = blockIdx.x * 32 + threadIdx.y;
    int c2 = blockIdx.y * 32 + threadIdx.x;
    feat[((size_t)i2 * 256 + n) * 128 + c2] = tile[threadIdx.x][threadIdx.y];
}

// ------------------------- batched pos_enc projection ----------------------
__global__ void proj_batch(const float* __restrict__ pos_enc,
                           const float* __restrict__ s_iw, const float* __restrict__ s_ib,
                           const float* __restrict__ c_iw, const float* __restrict__ c_ib,
                           __nv_bfloat16* __restrict__ out)
{
    int z = blockIdx.z, layer = z >> 1;
    const float* B    = ((z & 1) ? c_iw : s_iw) + (size_t)layer * 384 * 128;
    const float* bias = ((z & 1) ? c_ib : s_ib) + layer * 384;
    __nv_bfloat16* C = out + (size_t)z * 383 * 256;
    const int M = 383, N = 256;
    const float qsc = 0.17677669529663687f;

    __shared__ float As[16][68];
    __shared__ float Bs[16][68];
    int tid = threadIdx.x;
    int tx = tid & 15, ty = tid >> 4;
    int rowBase = blockIdx.y * 64;
    int colBase = blockIdx.x * 64;

    float acc[4][4];
    #pragma unroll
    for (int i = 0; i < 4; i++)
        #pragma unroll
        for (int j = 0; j < 4; j++) acc[i][j] = 0.f;

    int lr = tid >> 2;
    int lc = (tid & 3) * 4;
    int ar = rowBase + lr;
    const float* aRowPtr = (ar < M) ? (pos_enc + (size_t)ar * 128) : nullptr;
    int bc = colBase + lr;
    const float* bRowPtr = (bc < N) ? (B + (size_t)bc * 128) : nullptr;

    for (int kt = 0; kt < 8; kt++) {
        int k0 = kt * 16 + lc;
        float4 av = aRowPtr ? *(const float4*)(aRowPtr + k0) : make_float4(0, 0, 0, 0);
        float4 bv = bRowPtr ? *(const float4*)(bRowPtr + k0) : make_float4(0, 0, 0, 0);
        As[lc + 0][lr] = av.x; As[lc + 1][lr] = av.y; As[lc + 2][lr] = av.z; As[lc + 3][lr] = av.w;
        Bs[lc + 0][lr] = bv.x; Bs[lc + 1][lr] = bv.y; Bs[lc + 2][lr] = bv.z; Bs[lc + 3][lr] = bv.w;
        __syncthreads();
        #pragma unroll
        for (int k = 0; k < 16; k++) {
            float a0 = As[k][ty * 4 + 0], a1 = As[k][ty * 4 + 1];
            float a2 = As[k][ty * 4 + 2], a3 = As[k][ty * 4 + 3];
            float b0 = Bs[k][tx * 4 + 0], b1 = Bs[k][tx * 4 + 1];
            float b2 = Bs[k][tx * 4 + 2], b3 = Bs[k][tx * 4 + 3];
            acc[0][0] = fmaf(a0, b0, acc[0][0]); acc[0][1] = fmaf(a0, b1, acc[0][1]);
            acc[0][2] = fmaf(a0, b2, acc[0][2]); acc[0][3] = fmaf(a0, b3, acc[0][3]);
            acc[1][0] = fmaf(a1, b0, acc[1][0]); acc[1][1] = fmaf(a1, b1, acc[1][1]);
            acc[1][2] = fmaf(a1, b2, acc[1][2]); acc[1][3] = fmaf(a1, b3, acc[1][3]);
            acc[2][0] = fmaf(a2, b0, acc[2][0]); acc[2][1] = fmaf(a2, b1, acc[2][1]);
            acc[2][2] = fmaf(a2, b2, acc[2][2]); acc[2][3] = fmaf(a2, b3, acc[2][3]);
            acc[3][0] = fmaf(a3, b0, acc[3][0]); acc[3][1] = fmaf(a3, b1, acc[3][1]);
            acc[3][2] = fmaf(a3, b2, acc[3][2]); acc[3][3] = fmaf(a3, b3, acc[3][3]);
        }
        __syncthreads();
    }

    #pragma unroll
    for (int mi = 0; mi < 4; mi++) {
        int r = rowBase + ty * 4 + mi;
        if (r >= M) continue;
        __nv_bfloat16* cRow = C + (size_t)r * 256;
        #pragma unroll
        for (int ni = 0; ni < 4; ni++) {
            int col = colBase + tx * 4 + ni;
            float v = acc[mi][ni] + bias[col];
            if (col < 128) v *= qsc;
            cRow[col] = __float2bfloat16(v);
        }
    }
}

// ------------------------- bf16 tensor-core GEMM core ----------------------
#define HSMEM (2 * 128 * 128 * 2)

template<int AMODE>
__device__ __forceinline__ void hgemm_body(
    const void* __restrict__ Av, int aN0, int aNW, int aNF,
    const float* __restrict__ lnG, const float* __restrict__ lnB,
    const __nv_bfloat16* __restrict__ B, const float* __restrict__ bias,
    float* __restrict__ C, __nv_bfloat16* __restrict__ Cbf,
    int cN0, int cNW, int cNF, int cPitch,
    int addRes, int scaleLim, int rowBase, int colBase,
    __nv_bfloat16* As, __nv_bfloat16* Bs)
{
    int tid = threadIdx.x;
    unsigned asBase = (unsigned)__cvta_generic_to_shared(As);
    unsigned bsBase = (unsigned)__cvta_generic_to_shared(Bs);
    int lr = tid >> 1, lkh = tid & 1;
    {
        int ar = rowBase + lr;
        int arow = (ar / aNW) * aNF + aN0 + (ar % aNW);
        const __nv_bfloat16* bp = B + (size_t)(colBase + lr) * 128 + lkh * 64;
        int sw = lr & 7;

        // ---- B via cp.async (overlaps with A processing below) ----
        #pragma unroll
        for (int j = 0; j < 8; j++) {
            int cp = (lkh * 8 + j) ^ sw;
            cpasync16(bsBase + (unsigned)((lr * 128 + cp * 8) * 2), bp + j * 8);
        }
        asm volatile("cp.async.commit_group;");

        float mean = 0.f, inv = 1.f;
        if (AMODE == 1) {
            const float* ap = (const float*)Av + (size_t)arow * 128 + lkh * 64;
            float s = 0.f, sq = 0.f;
            #pragma unroll
            for (int j = 0; j < 16; j++) {
                float4 v = *(const float4*)(ap + j * 4);
                s += v.x + v.y + v.z + v.w;
                sq += v.x*v.x + v.y*v.y + v.z*v.z + v.w*v.w;
            }
            s  += __shfl_xor_sync(0xffffffffu, s,  1);
            sq += __shfl_xor_sync(0xffffffffu, sq, 1);
            mean = s * (1.f / 128.f);
            float var = sq * (1.f / 128.f) - mean * mean;
            inv = rsqrtf(var + 1e-5f);
        }

        #pragma unroll
        for (int j = 0; j < 8; j++) {
            int c = lkh * 8 + j;
            int cp = c ^ sw;
            if (AMODE == 2) {
                const __nv_bfloat16* ap = (const __nv_bfloat16*)Av + (size_t)arow * 128 + lkh * 64;
                cpasync16(asBase + (unsigned)((lr * 128 + cp * 8) * 2), ap + j * 8);
            } else {
                const float* ap = (const float*)Av + (size_t)arow * 128 + lkh * 64;
                float4 v0 = *(const float4*)(ap + j * 8);
                float4 v1 = *(const float4*)(ap + j * 8 + 4);
                int ch = lkh * 64 + j * 8;
                float4 g0 = *(const float4*)(lnG + ch), g1 = *(const float4*)(lnG + ch + 4);
                float4 b0 = *(const float4*)(lnB + ch), b1 = *(const float4*)(lnB + ch + 4);
                v0.x = (v0.x - mean) * inv * g0.x + b0.x;
                v0.y = (v0.y - mean) * inv * g0.y + b0.y;
                v0.z = (v0.z - mean) * inv * g0.z + b0.z;
                v0.w = (v0.w - mean) * inv * g0.w + b0.w;
                v1.x = (v1.x - mean) * inv * g1.x + b1.x;
                v1.y = (v1.y - mean) * inv * g1.y + b1.y;
                v1.z = (v1.z - mean) * inv * g1.z + b1.z;
                v1.w = (v1.w - mean) * inv * g1.w + b1.w;
                uint4 u;
                u.x = pack_bf2(v0.x, v0.y); u.y = pack_bf2(v0.z, v0.w);
                u.z = pack_bf2(v1.x, v1.y); u.w = pack_bf2(v1.z, v1.w);
                *(uint4*)&As[lr * 128 + cp * 8] = u;
            }
        }
        if (AMODE == 2) asm volatile("cp.async.commit_group;");
        asm volatile("cp.async.wait_group 0;");
    }
    __syncthreads();

    int wid = tid >> 5, lane = tid & 31;
    int wm = (wid & 3) * 32;
    int wn = (wid >> 2) * 64;
    int g = lane >> 2, tg = lane & 3;

    float acc[2][8][4];
    #pragma unroll
    for (int mt = 0; mt < 2; mt++)
        #pragma unroll
        for (int nt = 0; nt < 8; nt++)
            #pragma unroll
            for (int q = 0; q < 4; q++) acc[mt][nt][q] = 0.f;

    #pragma unroll
    for (int ks = 0; ks < 8; ks++) {
        int c0 = ks * 2;
        unsigned afr[2][4];
        #pragma unroll
        for (int mt = 0; mt < 2; mt++) {
            int row = wm + mt * 16 + (lane & 15);
            int ch = c0 + (lane >> 4);
            unsigned addr = asBase + (unsigned)((row * 128 + ((ch ^ (row & 7)) << 3)) * 2);
            ldm4(afr[mt][0], afr[mt][1], afr[mt][2], afr[mt][3], addr);
        }
        unsigned bfr[8][2];
        #pragma unroll
        for (int p = 0; p < 4; p++) {
            int row = wn + p * 16 + (lane & 7) + ((lane >> 4) << 3);
            int ch = c0 + ((lane >> 3) & 1);
            unsigned addr = bsBase + (unsigned)((row * 128 + ((ch ^ (row & 7)) << 3)) * 2);
            unsigned r0, r1, r2, r3;
            ldm4(r0, r1, r2, r3, addr);
            bfr[p * 2][0] = r0;     bfr[p * 2][1] = r1;
            bfr[p * 2 + 1][0] = r2; bfr[p * 2 + 1][1] = r3;
        }
        #pragma unroll
        for (int mt = 0; mt < 2; mt++)
            #pragma unroll
            for (int nt = 0; nt < 8; nt++)
                mma_bf16(acc[mt][nt], afr[mt], bfr[nt][0], bfr[nt][1]);
    }

    const float qsc = 0.17677669529663687f;
    #pragma unroll
    for (int mt = 0; mt < 2; mt++) {
        int r0g = rowBase + wm + mt * 16 + g;
        #pragma unroll
        for (int half = 0; half < 2; half++) {
            int r = r0g + half * 8;
            int crow = (r / cNW) * cNF + cN0 + (r % cNW);
            #pragma unroll
            for (int nt = 0; nt < 8; nt++) {
                int col = colBase + wn + nt * 8 + 2 * tg;
                float2 b2 = *(const float2*)(bias + col);
                float vx = acc[mt][nt][half * 2 + 0] + b2.x;
                float vy = acc[mt][nt][half * 2 + 1] + b2.y;
                if (Cbf) {
                    if (col < scaleLim) { vx *= qsc; vy *= qsc; }
                    *(unsigned*)(Cbf + (size_t)crow * cPitch + col) = pack_bf2(vx, vy);
                } else {
                    float* cp = C + (size_t)crow * cPitch + col;
                    if (addRes) {
                        float2 old = *(const float2*)cp;
                        vx += old.x; vy += old.y;
                    }
                    float2 o2; o2.x = vx; o2.y = vy;
                    *(float2*)cp = o2;
                }
            }
        }
    }
}

template<int AMODE>
__global__ void __launch_bounds__(256) hgemm(
    const void* __restrict__ Av, int aN0, int aNW, int aNF,
    const float* __restrict__ lnG, const float* __restrict__ lnB,
    const __nv_bfloat16* __restrict__ B, const float* __restrict__ bias,
    float* __restrict__ C, __nv_bfloat16* __restrict__ Cbf,
    int cN0, int cNW, int cNF, int cPitch,
    int addRes, int scaleLim)
{
    extern __shared__ __nv_bfloat16 hsm[];
    hgemm_body<AMODE>(Av, aN0, aNW, aNF, lnG, lnB, B, bias, C, Cbf,
                      cN0, cNW, cNF, cPitch, addRes, scaleLim,
                      blockIdx.y * 128, blockIdx.x * 128, hsm, hsm + 128*128);
}

__global__ void __launch_bounds__(256) hgemm_cross(
    const float* __restrict__ feat, int qN0, int kN0,
    const float* __restrict__ lnGq, const float* __restrict__ lnBq,
    const float* __restrict__ lnGk, const float* __restrict__ lnBk,
    const __nv_bfloat16* __restrict__ ciw, const float* __restrict__ cib,
    __nv_bfloat16* __restrict__ outQ, __nv_bfloat16* __restrict__ outKV)
{
    extern __shared__ __nv_bfloat16 hsm[];
    int x = blockIdx.x;
    if (x == 0) {
        hgemm_body<1>(feat, qN0, 128, 256, lnGq, lnBq, ciw, cib,
                      nullptr, outQ, 0, 128, 128, 128, 0, 128,
                      blockIdx.y * 128, 0, hsm, hsm + 128*128);
    } else {
        hgemm_body<1>(feat, kN0, 128, 256, lnGk, lnBk, ciw + 128 * 128, cib + 128,
                      nullptr, outKV, 0, 128, 128, 256, 0, 0,
                      blockIdx.y * 128, (x - 1) * 128, hsm, hsm + 128*128);
    }
}

// Merged post-cross1: x=0 -> out-proj of fr-attention (rows n>=128),
// x=1 -> fl-q projection (rows n<128). Disjoint feat rows.
__global__ void __launch_bounds__(256) hgemm_post1(
    const __nv_bfloat16* __restrict__ voh,
    const __nv_bfloat16* __restrict__ cow, const float* __restrict__ cob,
    float* __restrict__ feat,
    const float* __restrict__ lnG, const float* __restrict__ lnB,
    const __nv_bfloat16* __restrict__ ciw, const float* __restrict__ cib,
    __nv_bfloat16* __restrict__ outQ)
{
    extern __shared__ __nv_bfloat16 hsm[];
    if (blockIdx.x == 0) {
        hgemm_body<2>(voh, 0, 128, 128, nullptr, nullptr, cow, cob,
                      feat, nullptr, 128, 128, 256, 128, 1, 0,
                      blockIdx.y * 128, 0, hsm, hsm + 128*128);
    } else {
        hgemm_body<1>(feat, 0, 128, 256, lnG, lnB, ciw, cib,
                      nullptr, outQ, 0, 128, 128, 128, 0, 128,
                      blockIdx.y * 128, 0, hsm, hsm + 128*128);
    }
}

// ------------------------- bf16 mma attention (48-row blocks) ---------------
// smem: Qs@0 (3840), Ks@3840 (15360; Opart overlays), PBs@19200 (19200:
//   PK -> PQ -> Vt), Ssm@38400 (37632 -> packed P), hsum@76032 (384).
//   Total 76416 -> 3 blocks/SM. All copy phases via cp.async.
#define ATC_SMEM 76416

template<int DSIGN>
__global__ void __launch_bounds__(256, 3) attn_tc(
    const __nv_bfloat16* __restrict__ qPtr, int qPitch, int qOff,
    const __nv_bfloat16* __restrict__ kPtr, int kPitch, int kOff,
    const __nv_bfloat16* __restrict__ vPtr, int vPitch, int vOff,
    const __nv_bfloat16* __restrict__ proj, __nv_bfloat16* __restrict__ vo, int nB)
{
    extern __shared__ char smraw[];
    __nv_bfloat16* Qs  = (__nv_bfloat16*)(smraw);
    __nv_bfloat16* Ks  = (__nv_bfloat16*)(smraw + 3840);
    __nv_bfloat16* PBs = (__nv_bfloat16*)(smraw + 19200);  // PK -> PQ -> Vt
    __nv_bfloat16* Vt  = PBs;
    float* Opart = (float*)(smraw + 3840);                 // overlay Ks
    float* Ssm  = (float*)(smraw + 38400);
    float* hsum = (float*)(smraw + 76032);                 // [2][48]

    int n = blockIdx.x, e = blockIdx.y;
    int i0 = blockIdx.z * 48;
    int tid = threadIdx.x;
    const int dlo = (DSIGN > 0) ? (144 - i0) : i0;

    unsigned qBase  = (unsigned)__cvta_generic_to_shared(Qs);
    unsigned kBase  = (unsigned)__cvta_generic_to_shared(Ks);
    unsigned pbBase = (unsigned)__cvta_generic_to_shared(PBs);
    unsigned vtBase = pbBase;
    unsigned pBase  = (unsigned)__cvta_generic_to_shared(Ssm);

    // ---- loads: Q, K, PK — all cp.async 16B copies ----
    for (int idx = tid; idx < 48 * 4; idx += 256) {
        int r = idx >> 2, h = (idx & 3) * 8;
        cpasync16(qBase + (unsigned)((r * 40 + h) * 2),
                  qPtr + (size_t)((i0 + r) * nB + n) * qPitch + qOff + e * 32 + h);
    }
    for (int idx = tid; idx < 192 * 4; idx += 256) {
        int r = idx >> 2, h = (idx & 3) * 8;
        cpasync16(kBase + (unsigned)((r * 40 + h) * 2),
                  kPtr + (size_t)(r * nB + n) * kPitch + kOff + e * 32 + h);
    }
    for (int idx = tid; idx < 240 * 4; idx += 256) {
        int t = idx >> 2, h = (idx & 3) * 8;
        int d = dlo + t;
        int dc = (d < 383) ? d : 0;
        cpasync16z(pbBase + (unsigned)((t * 40 + h) * 2),
                   proj + (size_t)dc * 256 + 128 + e * 32 + h,
                   (d < 383) ? 16 : 0);
    }
    asm volatile("cp.async.commit_group;");
    asm volatile("cp.async.wait_group 0;");
    __syncthreads();

    int wid = tid >> 5, lane = tid & 31;
    int g = lane >> 2, tg = lane & 3;

    // ---- Z1 = Q @ PK^T, skew-scattered (init): 3 m-tiles x 13 n16-tiles ----
    #pragma unroll 2
    for (int u = wid; u < 39; u += 8) {
        int mt = u / 13, nt = u % 13;
        int t0m = (DSIGN > 0) ? (32 - 16 * mt) : (16 * mt);
        int tb = t0m + nt * 16;
        unsigned a[2][4], b[2][4];
        #pragma unroll
        for (int ks = 0; ks < 2; ks++) {
            unsigned addrA = qBase + (unsigned)((mt * 16 + (lane & 15)) * 80 + (ks * 2 + (lane >> 4)) * 16);
            ldm4(a[ks][0], a[ks][1], a[ks][2], a[ks][3], addrA);
            int row = tb + (lane & 7) + ((lane >> 4) << 3);
            unsigned addrB = pbBase + (unsigned)(row * 80 + (ks * 2 + ((lane >> 3) & 1)) * 16);
            ldm4(b[ks][0], b[ks][1], b[ks][2], b[ks][3], addrB);
        }
        float acc[2][4];
        #pragma unroll
        for (int h = 0; h < 2; h++) { acc[h][0] = acc[h][1] = acc[h][2] = acc[h][3] = 0.f; }
        mma_bf16(acc[0], a[0], b[0][0], b[0][1]); mma_bf16(acc[0], a[1], b[1][0], b[1][1]);
        mma_bf16(acc[1], a[0], b[0][2], b[0][3]); mma_bf16(acc[1], a[1], b[1][2], b[1][3]);

        if (nt >= 1 && nt <= 11) {
            #pragma unroll
            for (int h = 0; h < 2; h++) {
                int t = tb + h * 8 + 2 * tg;
                #pragma unroll
                for (int rr = 0; rr < 2; rr++) {
                    int il = mt * 16 + g + 8 * rr;
                    float* row = &Ssm[il * 196];
                    if (DSIGN > 0) {
                        int j0 = t + il - 47;
                        row[j0]     = acc[h][rr * 2 + 0];
                        row[j0 + 1] = acc[h][rr * 2 + 1];
                    } else {
                        int j0 = 191 + il - t;
                        row[j0]     = acc[h][rr * 2 + 0];
                        row[j0 - 1] = acc[h][rr * 2 + 1];
                    }
                }
            }
        } else {
            #pragma unroll
            for (int h = 0; h < 2; h++) {
                int t = tb + h * 8 + 2 * tg;
                #pragma unroll
                for (int rr = 0; rr < 2; rr++) {
                    int il = mt * 16 + g + 8 * rr;
                    int j0 = (DSIGN > 0) ? (t + il - 47) : (191 + il - t);
                    int j1 = (DSIGN > 0) ? (j0 + 1) : (j0 - 1);
                    if ((unsigned)j0 < 192u) Ssm[il * 196 + j0] = acc[h][rr * 2 + 0];
                    if ((unsigned)j1 < 192u) Ssm[il * 196 + j1] = acc[h][rr * 2 + 1];
                }
            }
        }
    }
    __syncthreads();

    // ---- reload shared buffer with PQ (cp.async) ----
    for (int idx = tid; idx < 240 * 4; idx += 256) {
        int t = idx >> 2, h = (idx & 3) * 8;
        int d = dlo + t;
        int dc = (d < 383) ? d : 0;
        cpasync16z(pbBase + (unsigned)((t * 40 + h) * 2),
                   proj + (size_t)dc * 256 + e * 32 + h,
                   (d < 383) ? 16 : 0);
    }
    asm volatile("cp.async.commit_group;");
    asm volatile("cp.async.wait_group 0;");
    __syncthreads();

    // ---- Z2 = K @ PQ^T, skew scatter-ADD: 12 j-tiles x 4 n16-tiles ----
    #pragma unroll 2
    for (int u = wid; u < 48; u += 8) {
        int jt = u >> 2, nt = u & 3;
        int t0m = (DSIGN > 0) ? (16 * jt) : (176 - 16 * jt);
        int tb = t0m + nt * 16;
        unsigned a[2][4], b[2][4];
        #pragma unroll
        for (int ks = 0; ks < 2; ks++) {
            unsigned addrA = kBase + (unsigned)((jt * 16 + (lane & 15)) * 80 + (ks * 2 + (lane >> 4)) * 16);
            ldm4(a[ks][0], a[ks][1], a[ks][2], a[ks][3], addrA);
            int row = tb + (lane & 7) + ((lane >> 4) << 3);
            unsigned addrB = pbBase + (unsigned)(row * 80 + (ks * 2 + ((lane >> 3) & 1)) * 16);
            ldm4(b[ks][0], b[ks][1], b[ks][2], b[ks][3], addrB);
        }
        float acc[2][4];
        #pragma unroll
        for (int h = 0; h < 2; h++) { acc[h][0] = acc[h][1] = acc[h][2] = acc[h][3] = 0.f; }
        mma_bf16(acc[0], a[0], b[0][0], b[0][1]); mma_bf16(acc[0], a[1], b[1][0], b[1][1]);
        mma_bf16(acc[1], a[0], b[0][2], b[0][3]); mma_bf16(acc[1], a[1], b[1][2], b[1][3]);

        if (nt == 1 || nt == 2) {
            #pragma unroll
            for (int h = 0; h < 2; h++) {
                int t = tb + h * 8 + 2 * tg;
                #pragma unroll
                for (int rr = 0; rr < 2; rr++) {
                    int j = jt * 16 + g + 8 * rr;
                    int il0 = (DSIGN > 0) ? (47 + j - t) : (t + j - 191);
                    int il1 = (DSIGN > 0) ? (il0 - 1) : (il0 + 1);
                    Ssm[il0 * 196 + j] += acc[h][rr * 2 + 0];
                    Ssm[il1 * 196 + j] += acc[h][rr * 2 + 1];
                }
            }
        } else {
            #pragma unroll
            for (int h = 0; h < 2; h++) {
                int t = tb + h * 8 + 2 * tg;
                #pragma unroll
                for (int rr = 0; rr < 2; rr++) {
                    int j = jt * 16 + g + 8 * rr;
                    int il0 = (DSIGN > 0) ? (47 + j - t) : (t + j - 191);
                    int il1 = (DSIGN > 0) ? (il0 - 1) : (il0 + 1);
                    if ((unsigned)il0 < 48u) Ssm[il0 * 196 + j] += acc[h][rr * 2 + 0];
                    if ((unsigned)il1 < 48u) Ssm[il1 * 196 + j] += acc[h][rr * 2 + 1];
                }
            }
        }
    }
    __syncthreads();

    // ---- warps 0-5: QK^T + gather + exp + partial sums. warps 6-7: Vt ----
    float acc[12][4];
    int mt = wid >> 1, chalf = wid & 1;
    int ilA = mt * 16 + g, ilB = ilA + 8;
    if (wid < 6) {
        #pragma unroll
        for (int nt = 0; nt < 12; nt++)
            #pragma unroll
            for (int q = 0; q < 4; q++) acc[nt][q] = 0.f;

        unsigned a[2][4];
        #pragma unroll
        for (int ks = 0; ks < 2; ks++) {
            unsigned addrA = qBase + (unsigned)((mt * 16 + (lane & 15)) * 80 + (ks * 2 + (lane >> 4)) * 16);
            ldm4(a[ks][0], a[ks][1], a[ks][2], a[ks][3], addrA);
        }
        #pragma unroll
        for (int nt16 = 0; nt16 < 6; nt16++) {
            unsigned b[2][4];
            #pragma unroll
            for (int ks = 0; ks < 2; ks++) {
                int row = chalf * 96 + nt16 * 16 + (lane & 7) + ((lane >> 4) << 3);
                unsigned addrB = kBase + (unsigned)(row * 80 + (ks * 2 + ((lane >> 3) & 1)) * 16);
                ldm4(b[ks][0], b[ks][1], b[ks][2], b[ks][3], addrB);
            }
            mma_bf16(acc[nt16 * 2],     a[0], b[0][0], b[0][1]);
            mma_bf16(acc[nt16 * 2],     a[1], b[1][0], b[1][1]);
            mma_bf16(acc[nt16 * 2 + 1], a[0], b[0][2], b[0][3]);
            mma_bf16(acc[nt16 * 2 + 1], a[1], b[1][2], b[1][3]);
        }

        float sA = 0.f, sB = 0.f;
        #pragma unroll
        for (int nt = 0; nt < 12; nt++) {
            int j = chalf * 96 + nt * 8 + 2 * tg;
            float2 zA = *(const float2*)&Ssm[ilA * 196 + j];
            float2 zB = *(const float2*)&Ssm[ilB * 196 + j];
            acc[nt][0] = __expf(fminf(acc[nt][0] + zA.x, 70.f)); sA += acc[nt][0];
            acc[nt][1] = __expf(fminf(acc[nt][1] + zA.y, 70.f)); sA += acc[nt][1];
            acc[nt][2] = __expf(fminf(acc[nt][2] + zB.x, 70.f)); sB += acc[nt][2];
            acc[nt][3] = __expf(fminf(acc[nt][3] + zB.y, 70.f)); sB += acc[nt][3];
        }
        sA += __shfl_xor_sync(0xffffffffu, sA, 1);
        sA += __shfl_xor_sync(0xffffffffu, sA, 2);
        sB += __shfl_xor_sync(0xffffffffu, sB, 1);
        sB += __shfl_xor_sync(0xffffffffu, sB, 2);
        if (tg == 0) {
            hsum[chalf * 48 + ilA] = sA;
            hsum[chalf * 48 + ilB] = sB;
        }
    } else {
        // transpose-load V into the dead PBs region; XOR-swizzled j-chunks
        for (int idx = tid - 192; idx < 192 * 4; idx += 64) {
            int j = idx >> 2, c8 = (idx & 3) * 8;
            uint4 u = *(const uint4*)(vPtr + (size_t)(j * nB + n) * vPitch + vOff + e * 32 + c8);
            __nv_bfloat16 tmp[8];
            *(uint4*)tmp = u;
            int chunk = j >> 3, jo = j & 7;
            #pragma unroll
            for (int k = 0; k < 8; k++) {
                int row = c8 + k;
                int cs = chunk ^ ((row >> 3) & 3);
                Vt[row * 200 + cs * 8 + jo] = tmp[k];
            }
        }
    }
    __syncthreads();

    // ---- normalize, write P (packed bf16 over Ssm); pair-scoped barriers ----
    if (wid < 6) {
        float invA = 1.f / (hsum[ilA] + hsum[48 + ilA]);
        float invB = 1.f / (hsum[ilB] + hsum[48 + ilB]);
        unsigned* Pw = (unsigned*)Ssm;
        #pragma unroll
        for (int nt = 0; nt < 12; nt++) {
            int cw = chalf * 48 + nt * 4 + tg;
            Pw[ilA * 196 + cw] = pack_bf2(acc[nt][0] * invA, acc[nt][1] * invA);
            Pw[ilB * 196 + cw] = pack_bf2(acc[nt][2] * invB, acc[nt][3] * invB);
        }
        asm volatile("bar.sync %0, 64;" :: "r"(mt + 1) : "memory");

        // ---- O = P @ V : 6 warps (3 m-tiles x 2 k-halves) ----
        float oacc[4][4];
        #pragma unroll
        for (int t = 0; t < 4; t++)
            #pragma unroll
            for (int q = 0; q < 4; q++) oacc[t][q] = 0.f;

        #pragma unroll 2
        for (int s = 0; s < 6; s++) {
            int ks = chalf * 6 + s;
            unsigned a[4];
            unsigned addrA = pBase + (unsigned)((mt * 16 + (lane & 15)) * 784 + (ks * 2 + (lane >> 4)) * 16);
            ldm4(a[0], a[1], a[2], a[3], addrA);
            #pragma unroll
            for (int nb = 0; nb < 2; nb++) {
                int row = nb * 16 + (lane & 7) + ((lane >> 4) << 3);
                int chunk = ks * 2 + ((lane >> 3) & 1);
                int cs = chunk ^ ((row >> 3) & 3);
                unsigned addrB = vtBase + (unsigned)(row * 400 + cs * 16);
                unsigned b0, b1, b2, b3;
                ldm4(b0, b1, b2, b3, addrB);
                mma_bf16(oacc[nb * 2],     a, b0, b1);
                mma_bf16(oacc[nb * 2 + 1], a, b2, b3);
            }
        }
        if (chalf == 1) {
            #pragma unroll
            for (int t = 0; t < 4; t++) {
                int c = t * 8 + 2 * tg;
                Opart[ilA * 32 + c]     = oacc[t][0];
                Opart[ilA * 32 + c + 1] = oacc[t][1];
                Opart[ilB * 32 + c]     = oacc[t][2];
                Opart[ilB * 32 + c + 1] = oacc[t][3];
            }
        }
        asm volatile("bar.sync %0, 64;" :: "r"(mt + 1) : "memory");

        if (chalf == 0) {
            int iA = i0 + ilA, iB = i0 + ilB;
            size_t oA = (size_t)(iA * nB + n) * 128 + e * 32;
            size_t oB = (size_t)(iB * nB + n) * 128 + e * 32;
            #pragma unroll
            for (int t = 0; t < 4; t++) {
                int c = t * 8 + 2 * tg;
                *(unsigned*)(vo + oA + c) = pack_bf2(oacc[t][0] + Opart[ilA * 32 + c],
                                                     oacc[t][1] + Opart[ilA * 32 + c + 1]);
                *(unsigned*)(vo + oB + c) = pack_bf2(oacc[t][2] + Opart[ilB * 32 + c],
                                                     oacc[t][3] + Opart[ilB * 32 + c + 1]);
            }
        }
    }
}

// ---------------------------------------------------------------------------
extern "C" void kernel_launch(void* const* d_in, const int* in_sizes, int n_in,
                              void* d_out, int out_size)
{
    (void)in_sizes; (void)n_in; (void)out_size;
    const float* feat_left  = (const float*)d_in[0];
    const float* feat_right = (const float*)d_in[1];
    const float* pos_enc    = (const float*)d_in[2];
    const float* s_iw = (const float*)d_in[3];
    const float* s_ib = (const float*)d_in[4];
    const float* s_ow = (const float*)d_in[5];
    const float* s_ob = (const float*)d_in[6];
    const float* s_g  = (const float*)d_in[7];
    const float* s_b  = (const float*)d_in[8];
    const float* c_iw = (const float*)d_in[9];
    const float* c_ib = (const float*)d_in[10];
    const float* c_ow = (const float*)d_in[11];
    const float* c_ob = (const float*)d_in[12];
    const float* c_g1 = (const float*)d_in[13];
    const float* c_b1 = (const float*)d_in[14];
    const float* c_g2 = (const float*)d_in[15];
    const float* c_b2 = (const float*)d_in[16];

    float* feat = (float*)d_out;

    __nv_bfloat16 *qkvh, *voh, *projb, *wbh;
    cudaGetSymbolAddress((void**)&qkvh, g_qkvh);
    cudaGetSymbolAddress((void**)&voh, g_voh);
    cudaGetSymbolAddress((void**)&projb, g_proj);
    cudaGetSymbolAddress((void**)&wbh, g_wbh);
    __nv_bfloat16* qbh  = qkvh;
    __nv_bfloat16* kvbh = qkvh + 192 * 128 * 128;

    cudaFuncSetAttribute(attn_tc<1>,  cudaFuncAttributeMaxDynamicSharedMemorySize, ATC_SMEM);
    cudaFuncSetAttribute(attn_tc<-1>, cudaFuncAttributeMaxDynamicSharedMemorySize, ATC_SMEM);
    cudaFuncSetAttribute(hgemm<1>, cudaFuncAttributeMaxDynamicSharedMemorySize, HSMEM);
    cudaFuncSetAttribute(hgemm<2>, cudaFuncAttributeMaxDynamicSharedMemorySize, HSMEM);
    cudaFuncSetAttribute(hgemm_cross, cudaFuncAttributeMaxDynamicSharedMemorySize, HSMEM);
    cudaFuncSetAttribute(hgemm_post1, cudaFuncAttributeMaxDynamicSharedMemorySize, HSMEM);

    build_feat<<<dim3(6, 4, 256), dim3(32, 32)>>>(feat_left, feat_right, feat);
    proj_batch<<<dim3(4, 6, 8), 256>>>(pos_enc, s_iw, s_ib, c_iw, c_ib, projb);
    cvt_bf16_all<<<dim3(192, 4), 256>>>(s_iw, s_ow, c_iw, c_ow, wbh);

    for (int L = 0; L < 4; L++) {
        const __nv_bfloat16* siwH = wbh + WOFF_SIW + (size_t)L * 384 * 128;
        const __nv_bfloat16* sowH = wbh + WOFF_SOW + (size_t)L * 128 * 128;
        const __nv_bfloat16* ciwH = wbh + WOFF_CIW + (size_t)L * 384 * 128;
        const __nv_bfloat16* cowH = wbh + WOFF_COW + (size_t)L * 128 * 128;
        const float* sib = s_ib + (size_t)L * 384;
        const float* sob = s_ob + (size_t)L * 128;
        const float* cib = c_ib + (size_t)L * 384;
        const float* cob = c_ob + (size_t)L * 128;
        const __nv_bfloat16* projS = projb + (size_t)(L * 2) * 383 * 256;
        const __nv_bfloat16* projC = projb + (size_t)(L * 2 + 1) * 383 * 256;

        // ---------------- self-attention ----------------
        hgemm<1><<<dim3(3, 384), 256, HSMEM>>>(feat, 0, 256, 256,
                                               s_g + L * 128, s_b + L * 128,
                                               siwH, sib, nullptr, qkvh,
                                               0, 256, 256, 384, 0, 128);
        attn_tc<1><<<dim3(256, 4, 4), 256, ATC_SMEM>>>(qkvh, 384, 0, qkvh, 384, 128,
                                                       qkvh, 384, 256, projS, voh, 256);
        hgemm<2><<<dim3(1, 384), 256, HSMEM>>>(voh, 0, 256, 256, nullptr, nullptr,
                                               sowH, sob, feat, nullptr,
                                               0, 256, 256, 128, 1, 0);

        // ---------------- cross-attention ----------------
        hgemm_cross<<<dim3(3, 192), 256, HSMEM>>>(feat, 128, 0,
                                                  c_g1 + L * 128, c_b1 + L * 128,
                                                  c_g1 + L * 128, c_b1 + L * 128,
                                                  ciwH, cib, qbh, kvbh);
        attn_tc<-1><<<dim3(128, 4, 4), 256, ATC_SMEM>>>(qbh, 128, 0, kvbh, 256, 0,
                                                        kvbh, 256, 128, projC, voh, 128);
        hgemm_post1<<<dim3(2, 192), 256, HSMEM>>>(voh, cowH, cob, feat,
                                                  c_g1 + L * 128, c_b1 + L * 128,
                                                  ciwH, cib, qbh);
        hgemm<1><<<dim3(2, 192), 256, HSMEM>>>(feat, 128, 128, 256,
                                               c_g2 + L * 128, c_b2 + L * 128,
                                               ciwH + 128 * 128, cib + 128, nullptr, kvbh,
                                               0, 128, 128, 256, 0, 0);
        attn_tc<1><<<dim3(128, 4, 4), 256, ATC_SMEM>>>(qbh, 128, 0, kvbh, 256, 0,
                                                       kvbh, 256, 128, projC, voh, 128);
        hgemm<2><<<dim3(1, 192), 256, HSMEM>>>(voh, 0, 128, 128, nullptr, nullptr,
                                               cowH, cob, feat, nullptr,
                                               0, 128, 256, 128, 1, 0);
    }
}